// round 1
// baseline (speedup 1.0000x reference)
#include <cuda_runtime.h>

#define NN 2048
#define FF 64
#define HH 128
#define TI 32
#define NB (NN/TI)            // 64
#define NPAIR (NB*(NB+1)/2)   // 2080
#define EDGEF 2096128.0       // NN*(NN-1)/2

typedef unsigned long long u64;

// ---------------- scratch (static device globals; no allocation) ----------------
__device__ float g_A1[NN*HH];
__device__ float g_A2[NN*HH];
__device__ float g_H3[NN*FF];
__device__ float g_W2f[HH*HH];
__device__ float g_b2f[HH];
__device__ float g_W3f[HH*FF];
__device__ float g_b3f[FF];
__device__ float g_W6f[HH*2];
__device__ float g_b6f[2];
__device__ double g_s1[HH], g_q1[HH], g_s2[HH], g_q2[HH], g_s5[HH], g_q5[HH];

__device__ __forceinline__ float lrelu(float x){ return x >= 0.f ? x : 0.01f*x; }
__device__ __forceinline__ u64 pk2(float x){ u64 r; asm("mov.b64 %0,{%1,%1};":"=l"(r):"f"(x)); return r; }
__device__ __forceinline__ u64 fma2(u64 a,u64 b,u64 c){ u64 d; asm("fma.rn.f32x2 %0,%1,%2,%3;":"=l"(d):"l"(a),"l"(b),"l"(c)); return d; }
__device__ __forceinline__ float2 up2(u64 v){ float2 f; asm("mov.b64 {%0,%1},%2;":"=f"(f.x),"=f"(f.y):"l"(v)); return f; }

// ---------------- init: zero stats + output diagonal ----------------
__global__ void k_init(float* __restrict__ out){
  int tid = threadIdx.x;
  if (tid < HH){
    g_s1[tid]=0.0; g_q1[tid]=0.0;
    g_s2[tid]=0.0; g_q2[tid]=0.0;
    g_s5[tid]=0.0; g_q5[tid]=0.0;
  }
  for (int i = tid; i < NN; i += blockDim.x){
    size_t d = (size_t)i*(NN+1)*2;
    out[d] = 0.f; out[d+1] = 0.f;
  }
}

// ---------------- node layer 1: A1 = lrelu(nf@W1+b1), stats1 ----------------
__global__ void k_node1(const float* __restrict__ nf, const float* __restrict__ W1,
                        const float* __restrict__ b1){
  __shared__ float nfs[TI*FF];                 // 8KB
  int tid = threadIdx.x;                       // 128 threads, one per output col
  int r0  = blockIdx.x*TI;
  for (int i = tid; i < TI*FF; i += 128) nfs[i] = nf[r0*FF + i];
  float w[FF];
  #pragma unroll
  for (int k = 0; k < FF; k++) w[k] = W1[k*HH + tid];
  float bc = b1[tid];
  __syncthreads();
  float s = 0.f, q = 0.f;
  for (int r = 0; r < TI; r++){
    float acc = bc;
    #pragma unroll
    for (int k = 0; k < FF; k++) acc += nfs[r*FF+k]*w[k];
    float a = lrelu(acc);
    g_A1[(r0+r)*HH + tid] = a;
    s += a; q += a*a;
  }
  atomicAdd(&g_s1[tid], (double)s);
  atomicAdd(&g_q1[tid], (double)q);
}

// ---------------- fold BN1 into W2 ----------------
__global__ void k_fold1(const float* __restrict__ W2, const float* __restrict__ b2,
                        const float* __restrict__ g1, const float* __restrict__ be1){
  __shared__ float al[HH], bt[HH];
  int tid = threadIdx.x;                       // 128 threads
  double m = g_s1[tid]/(double)NN;
  double v = g_q1[tid]/(double)NN - m*m;
  float a = rsqrtf((float)v + 1e-5f) * g1[tid];
  al[tid] = a; bt[tid] = be1[tid] - (float)m*a;
  __syncthreads();
  float bb = b2[tid];
  for (int k = 0; k < HH; k++){
    float w = W2[k*HH + tid];
    g_W2f[k*HH + tid] = al[k]*w;
    bb += bt[k]*w;
  }
  g_b2f[tid] = bb;
}

// ---------------- node layer 2: A2 = lrelu(A1@W2f+b2f), stats2 ----------------
__global__ void k_node2(){
  extern __shared__ float sm2[];
  float* w2s = sm2;               // 16384 floats
  float* a1s = sm2 + HH*HH;       // 4096 floats
  int tid = threadIdx.x;          // 128 threads
  int r0  = blockIdx.x*TI;
  for (int i = tid; i < HH*HH; i += 128) w2s[i] = g_W2f[i];
  for (int i = tid; i < TI*HH; i += 128) a1s[i] = g_A1[r0*HH + i];
  float bc = g_b2f[tid];
  __syncthreads();
  float s = 0.f, q = 0.f;
  for (int r = 0; r < TI; r++){
    float acc = bc;
    #pragma unroll 16
    for (int k = 0; k < HH; k++) acc += a1s[r*HH+k]*w2s[k*HH+tid];
    float a = lrelu(acc);
    g_A2[(r0+r)*HH + tid] = a;
    s += a; q += a*a;
  }
  atomicAdd(&g_s2[tid], (double)s);
  atomicAdd(&g_q2[tid], (double)q);
}

// ---------------- fold BN2 into W3 ----------------
__global__ void k_fold2(const float* __restrict__ W3, const float* __restrict__ b3,
                        const float* __restrict__ g2, const float* __restrict__ be2){
  __shared__ float al[HH], bt[HH];
  int tid = threadIdx.x;                       // 128 threads
  double m = g_s2[tid]/(double)NN;
  double v = g_q2[tid]/(double)NN - m*m;
  float a = rsqrtf((float)v + 1e-5f) * g2[tid];
  al[tid] = a; bt[tid] = be2[tid] - (float)m*a;
  __syncthreads();
  if (tid < FF){
    float bb = b3[tid];
    for (int k = 0; k < HH; k++){
      float w = W3[k*FF + tid];
      g_W3f[k*FF + tid] = al[k]*w;
      bb += bt[k]*w;
    }
    g_b3f[tid] = bb;
  }
}

// ---------------- node layer 3: H3 = A2@W3f + b3f + nf ----------------
__global__ void k_node3(const float* __restrict__ nf){
  __shared__ float a2s[TI*HH];   // 16KB
  __shared__ float w3s[HH*FF];   // 32KB  (total exactly 48KB static)
  int tid = threadIdx.x;         // 128 threads
  int r0  = blockIdx.x*TI;
  for (int i = tid; i < TI*HH; i += 128) a2s[i] = g_A2[r0*HH + i];
  for (int i = tid; i < HH*FF; i += 128) w3s[i] = g_W3f[i];
  __syncthreads();
  int c = tid & 63, rh = tid >> 6;
  for (int r = rh*16; r < rh*16 + 16; r++){
    float acc = g_b3f[c] + nf[(r0+r)*FF + c];
    #pragma unroll 16
    for (int k = 0; k < HH; k++) acc += a2s[r*HH+k]*w3s[k*FF+c];
    g_H3[(r0+r)*FF + c] = acc;
  }
}

// ---------------- edge kernel: PASS 1 = stats of t, PASS 2 = softmax output ----------------
// Pair-tile (bi<=bj) of 32x32 nodes. 256 threads. 16 chunks of 64 edges.
// Micro-tile: 4 edges x 8 cols per thread via 16 packed f32x2 accumulators.
template<int PASS>
__global__ void __launch_bounds__(256)
k_edge(const float* __restrict__ W5, const float* __restrict__ b5,
       float* __restrict__ out){
  extern __shared__ float sm[];
  float* W5s = sm;                  // 8192
  float* Hi  = W5s + FF*HH;         // 32*65 = 2080 (padded stride 65)
  float* Hj  = Hi + TI*65;          // 2080
  float* es  = Hj + TI*65;          // 64*64 = 4096
  float* b5s = es + 64*64;          // 128
  float* red = b5s + HH;            // 256
  int tid = threadIdx.x;

  // block -> (bi, bj), bi <= bj
  int p = blockIdx.x, bi = 0, rem = p;
  while (rem >= NB - bi){ rem -= NB - bi; bi++; }
  int bj = bi + rem;

  for (int i = tid; i < FF*HH; i += 256) W5s[i] = W5[i];
  for (int i = tid; i < TI*FF; i += 256){
    int r = i >> 6, k = i & 63;
    Hi[r*65 + k] = g_H3[(bi*TI + r)*FF + k];
    Hj[r*65 + k] = g_H3[(bj*TI + r)*FF + k];
  }
  if (tid < HH) b5s[tid] = b5[tid];
  red[tid] = 0.f;

  int cg = tid & 15;     // col group: cols cg*8 .. cg*8+7
  int eg = tid >> 4;     // edge group: edges 4*eg .. 4*eg+3 (of 64)

  float w60[8], w61[8];
  float b60 = 0.f, b61 = 0.f;
  if (PASS == 2){
    #pragma unroll
    for (int b = 0; b < 8; b++){
      w60[b] = g_W6f[(cg*8+b)*2];
      w61[b] = g_W6f[(cg*8+b)*2 + 1];
    }
    b60 = g_b6f[0]; b61 = g_b6f[1];
  }
  float ss[8], sq[8];
  #pragma unroll
  for (int b = 0; b < 8; b++){ ss[b] = 0.f; sq[b] = 0.f; }
  __syncthreads();

  for (int ii0 = 0; ii0 < TI; ii0 += 2){
    // stage e tile: es[k][m], m in [0,64): edge (ii0+(m>>5), m&31)
    #pragma unroll
    for (int t = 0; t < 16; t++){
      int idx = tid + t*256;
      int m = idx & 63, k = idx >> 6;
      int ii = ii0 + (m >> 5), jj = m & 31;
      es[k*64 + m] = Hi[ii*65 + k] * Hj[jj*65 + k];
    }
    __syncthreads();

    u64 acc[4][4];
    #pragma unroll
    for (int a = 0; a < 4; a++)
      #pragma unroll
      for (int pp = 0; pp < 4; pp++) acc[a][pp] = 0ull;

    const float4* es4 = (const float4*)es;
    #pragma unroll 8
    for (int k = 0; k < FF; k++){
      float4 ev = es4[k*16 + eg];
      ulonglong2 wA = *(const ulonglong2*)(W5s + k*HH + cg*8);
      ulonglong2 wB = *(const ulonglong2*)(W5s + k*HH + cg*8 + 4);
      u64 e0 = pk2(ev.x), e1 = pk2(ev.y), e2 = pk2(ev.z), e3 = pk2(ev.w);
      acc[0][0]=fma2(e0,wA.x,acc[0][0]); acc[0][1]=fma2(e0,wA.y,acc[0][1]);
      acc[0][2]=fma2(e0,wB.x,acc[0][2]); acc[0][3]=fma2(e0,wB.y,acc[0][3]);
      acc[1][0]=fma2(e1,wA.x,acc[1][0]); acc[1][1]=fma2(e1,wA.y,acc[1][1]);
      acc[1][2]=fma2(e1,wB.x,acc[1][2]); acc[1][3]=fma2(e1,wB.y,acc[1][3]);
      acc[2][0]=fma2(e2,wA.x,acc[2][0]); acc[2][1]=fma2(e2,wA.y,acc[2][1]);
      acc[2][2]=fma2(e2,wB.x,acc[2][2]); acc[2][3]=fma2(e2,wB.y,acc[2][3]);
      acc[3][0]=fma2(e3,wA.x,acc[3][0]); acc[3][1]=fma2(e3,wA.y,acc[3][1]);
      acc[3][2]=fma2(e3,wB.x,acc[3][2]); acc[3][3]=fma2(e3,wB.y,acc[3][3]);
    }

    float tv[4][8];
    #pragma unroll
    for (int a = 0; a < 4; a++)
      #pragma unroll
      for (int pp = 0; pp < 4; pp++){
        float2 v = up2(acc[a][pp]);
        tv[a][2*pp]   = lrelu(v.x + b5s[cg*8 + 2*pp]);
        tv[a][2*pp+1] = lrelu(v.y + b5s[cg*8 + 2*pp + 1]);
      }

    if (PASS == 1){
      #pragma unroll
      for (int a = 0; a < 4; a++){
        int m = 4*eg + a;
        int ii = ii0 + (m >> 5), jj = m & 31;
        if ((bi < bj) || (jj > ii)){
          #pragma unroll
          for (int b = 0; b < 8; b++){ ss[b] += tv[a][b]; sq[b] += tv[a][b]*tv[a][b]; }
        }
      }
    } else {
      float p0[4], p1[4];
      #pragma unroll
      for (int a = 0; a < 4; a++){
        float s0 = 0.f, s1 = 0.f;
        #pragma unroll
        for (int b = 0; b < 8; b++){ s0 += tv[a][b]*w60[b]; s1 += tv[a][b]*w61[b]; }
        p0[a] = s0; p1[a] = s1;
      }
      #pragma unroll
      for (int off = 8; off >= 1; off >>= 1){
        #pragma unroll
        for (int a = 0; a < 4; a++){
          p0[a] += __shfl_xor_sync(0xffffffffu, p0[a], off);
          p1[a] += __shfl_xor_sync(0xffffffffu, p1[a], off);
        }
      }
      if (cg < 4){
        int a = cg;
        int m = 4*eg + a;
        int ii = ii0 + (m >> 5), jj = m & 31;
        if ((bi < bj) || (jj > ii)){
          int gi = bi*TI + ii, gj = bj*TI + jj;
          float l0 = p0[a] + b60, l1 = p1[a] + b61;
          float mx = fmaxf(l0, l1);
          float q0 = expf(l0 - mx), q1 = expf(l1 - mx);
          float inv = 1.f/(q0 + q1);
          float2 pr = make_float2(q0*inv, q1*inv);
          float2* o2 = (float2*)out;
          o2[(size_t)gi*NN + gj] = pr;
          o2[(size_t)gj*NN + gi] = pr;
        }
      }
    }
    __syncthreads();
  }

  if (PASS == 1){
    #pragma unroll
    for (int b = 0; b < 8; b++){
      atomicAdd(&red[cg*8 + b], ss[b]);
      atomicAdd(&red[HH + cg*8 + b], sq[b]);
    }
    __syncthreads();
    if (tid < HH){
      atomicAdd(&g_s5[tid], (double)red[tid]);
      atomicAdd(&g_q5[tid], (double)red[HH + tid]);
    }
  }
}

// ---------------- fold BN5 into W6 ----------------
__global__ void k_fold5(const float* __restrict__ W6, const float* __restrict__ b6,
                        const float* __restrict__ g5, const float* __restrict__ be5){
  __shared__ float bt[HH];
  int tid = threadIdx.x;                       // 128 threads
  double m = g_s5[tid]/EDGEF;
  double v = g_q5[tid]/EDGEF - m*m;
  float a = rsqrtf((float)v + 1e-5f) * g5[tid];
  bt[tid] = be5[tid] - (float)m*a;
  g_W6f[tid*2]     = a*W6[tid*2];
  g_W6f[tid*2 + 1] = a*W6[tid*2 + 1];
  __syncthreads();
  if (tid < 2){
    float bb = b6[tid];
    for (int k = 0; k < HH; k++) bb += bt[k]*W6[k*2 + tid];
    g_b6f[tid] = bb;
  }
}

// ---------------- launch ----------------
extern "C" void kernel_launch(void* const* d_in, const int* in_sizes, int n_in,
                              void* d_out, int out_size){
  const float* nf  = (const float*)d_in[1];
  const float* W1  = (const float*)d_in[2];
  const float* b1  = (const float*)d_in[3];
  const float* g1  = (const float*)d_in[4];
  const float* be1 = (const float*)d_in[5];
  const float* W2  = (const float*)d_in[6];
  const float* b2  = (const float*)d_in[7];
  const float* g2  = (const float*)d_in[8];
  const float* be2 = (const float*)d_in[9];
  const float* W3  = (const float*)d_in[10];
  const float* b3  = (const float*)d_in[11];
  const float* W5  = (const float*)d_in[12];
  const float* b5  = (const float*)d_in[13];
  const float* g5  = (const float*)d_in[14];
  const float* be5 = (const float*)d_in[15];
  const float* W6  = (const float*)d_in[16];
  const float* b6  = (const float*)d_in[17];
  float* out = (float*)d_out;

  const int EDGE_SMEM = (FF*HH + 2*TI*65 + 64*64 + HH + 2*HH) * 4;   // 67328
  const int N2_SMEM   = (HH*HH + TI*HH) * 4;                          // 81920
  cudaFuncSetAttribute(k_edge<1>, cudaFuncAttributeMaxDynamicSharedMemorySize, EDGE_SMEM);
  cudaFuncSetAttribute(k_edge<2>, cudaFuncAttributeMaxDynamicSharedMemorySize, EDGE_SMEM);
  cudaFuncSetAttribute(k_node2,   cudaFuncAttributeMaxDynamicSharedMemorySize, N2_SMEM);

  k_init<<<1, 1024>>>(out);
  k_node1<<<NB, 128>>>(nf, W1, b1);
  k_fold1<<<1, 128>>>(W2, b2, g1, be1);
  k_node2<<<NB, 128, N2_SMEM>>>();
  k_fold2<<<1, 128>>>(W3, b3, g2, be2);
  k_node3<<<NB, 128>>>(nf);
  k_edge<1><<<NPAIR, 256, EDGE_SMEM>>>(W5, b5, out);
  k_fold5<<<1, 128>>>(W6, b6, g5, be5);
  k_edge<2><<<NPAIR, 256, EDGE_SMEM>>>(W5, b5, out);
}

// round 2
// speedup vs baseline: 1.4601x; 1.4601x over previous
#include <cuda_runtime.h>
#include <cuda_bf16.h>

#define NN 2048
#define FF 64
#define HH 128
#define TI 32
#define NB (NN/TI)            // 64
#define NPAIR (NB*(NB+1)/2)   // 2080
#define EDGEF 2096128.0       // NN*(NN-1)/2

typedef unsigned long long u64;

// ---------------- scratch (static device globals; no allocation) ----------------
__device__ float g_A1[NN*HH];
__device__ float g_A2[NN*HH];
__device__ float g_H3[NN*FF];
__device__ float g_W2f[HH*HH];
__device__ float g_b2f[HH];
__device__ float g_W3f[HH*FF];
__device__ float g_b3f[FF];
__device__ float g_W6f[HH*2];
__device__ float g_b6f[2];
__device__ double g_s1[HH], g_q1[HH], g_s2[HH], g_q2[HH], g_s5[HH], g_q5[HH];
// t-cache: NPAIR*1024 edge slots x 128 cols (fp32) = 1.09 GB
__device__ float4 g_T[(size_t)NPAIR*1024*32];

__device__ __forceinline__ float lrelu(float x){ return x >= 0.f ? x : 0.01f*x; }
__device__ __forceinline__ u64 pk2(float x){ u64 r; asm("mov.b64 %0,{%1,%1};":"=l"(r):"f"(x)); return r; }
__device__ __forceinline__ u64 fma2(u64 a,u64 b,u64 c){ u64 d; asm("fma.rn.f32x2 %0,%1,%2,%3;":"=l"(d):"l"(a),"l"(b),"l"(c)); return d; }
__device__ __forceinline__ float2 up2(u64 v){ float2 f; asm("mov.b64 {%0,%1},%2;":"=f"(f.x),"=f"(f.y):"l"(v)); return f; }

// ---------------- init: zero stats + output diagonal ----------------
__global__ void k_init(float* __restrict__ out){
  int tid = threadIdx.x;
  if (tid < HH){
    g_s1[tid]=0.0; g_q1[tid]=0.0;
    g_s2[tid]=0.0; g_q2[tid]=0.0;
    g_s5[tid]=0.0; g_q5[tid]=0.0;
  }
  for (int i = tid; i < NN; i += blockDim.x){
    size_t d = (size_t)i*(NN+1)*2;
    out[d] = 0.f; out[d+1] = 0.f;
  }
}

// ---------------- node layer 1: A1 = lrelu(nf@W1+b1), stats1 ----------------
__global__ void k_node1(const float* __restrict__ nf, const float* __restrict__ W1,
                        const float* __restrict__ b1){
  __shared__ float nfs[TI*FF];
  int tid = threadIdx.x;                       // 128 threads, one per output col
  int r0  = blockIdx.x*TI;
  for (int i = tid; i < TI*FF; i += 128) nfs[i] = nf[r0*FF + i];
  float w[FF];
  #pragma unroll
  for (int k = 0; k < FF; k++) w[k] = W1[k*HH + tid];
  float bc = b1[tid];
  __syncthreads();
  float s = 0.f, q = 0.f;
  for (int r = 0; r < TI; r++){
    float acc = bc;
    #pragma unroll
    for (int k = 0; k < FF; k++) acc += nfs[r*FF+k]*w[k];
    float a = lrelu(acc);
    g_A1[(r0+r)*HH + tid] = a;
    s += a; q += a*a;
  }
  atomicAdd(&g_s1[tid], (double)s);
  atomicAdd(&g_q1[tid], (double)q);
}

// ---------------- fold BN1 into W2 ----------------
__global__ void k_fold1(const float* __restrict__ W2, const float* __restrict__ b2,
                        const float* __restrict__ g1, const float* __restrict__ be1){
  __shared__ float al[HH], bt[HH];
  int tid = threadIdx.x;
  double m = g_s1[tid]/(double)NN;
  double v = g_q1[tid]/(double)NN - m*m;
  float a = rsqrtf((float)v + 1e-5f) * g1[tid];
  al[tid] = a; bt[tid] = be1[tid] - (float)m*a;
  __syncthreads();
  float bb = b2[tid];
  for (int k = 0; k < HH; k++){
    float w = W2[k*HH + tid];
    g_W2f[k*HH + tid] = al[k]*w;
    bb += bt[k]*w;
  }
  g_b2f[tid] = bb;
}

// ---------------- node layer 2: A2 = lrelu(A1@W2f+b2f), stats2 ----------------
__global__ void k_node2(){
  extern __shared__ float sm2[];
  float* w2s = sm2;               // 16384 floats
  float* a1s = sm2 + HH*HH;       // 4096 floats
  int tid = threadIdx.x;          // 128 threads
  int r0  = blockIdx.x*TI;
  for (int i = tid; i < HH*HH; i += 128) w2s[i] = g_W2f[i];
  for (int i = tid; i < TI*HH; i += 128) a1s[i] = g_A1[r0*HH + i];
  float bc = g_b2f[tid];
  __syncthreads();
  float s = 0.f, q = 0.f;
  for (int r = 0; r < TI; r++){
    float acc = bc;
    #pragma unroll 16
    for (int k = 0; k < HH; k++) acc += a1s[r*HH+k]*w2s[k*HH+tid];
    float a = lrelu(acc);
    g_A2[(r0+r)*HH + tid] = a;
    s += a; q += a*a;
  }
  atomicAdd(&g_s2[tid], (double)s);
  atomicAdd(&g_q2[tid], (double)q);
}

// ---------------- fold BN2 into W3 ----------------
__global__ void k_fold2(const float* __restrict__ W3, const float* __restrict__ b3,
                        const float* __restrict__ g2, const float* __restrict__ be2){
  __shared__ float al[HH], bt[HH];
  int tid = threadIdx.x;
  double m = g_s2[tid]/(double)NN;
  double v = g_q2[tid]/(double)NN - m*m;
  float a = rsqrtf((float)v + 1e-5f) * g2[tid];
  al[tid] = a; bt[tid] = be2[tid] - (float)m*a;
  __syncthreads();
  if (tid < FF){
    float bb = b3[tid];
    for (int k = 0; k < HH; k++){
      float w = W3[k*FF + tid];
      g_W3f[k*FF + tid] = al[k]*w;
      bb += bt[k]*w;
    }
    g_b3f[tid] = bb;
  }
}

// ---------------- node layer 3: H3 = A2@W3f + b3f + nf ----------------
__global__ void k_node3(const float* __restrict__ nf){
  __shared__ float a2s[TI*HH];   // 16KB
  __shared__ float w3s[HH*FF];   // 32KB
  int tid = threadIdx.x;         // 128 threads
  int r0  = blockIdx.x*TI;
  for (int i = tid; i < TI*HH; i += 128) a2s[i] = g_A2[r0*HH + i];
  for (int i = tid; i < HH*FF; i += 128) w3s[i] = g_W3f[i];
  __syncthreads();
  int c = tid & 63, rh = tid >> 6;
  for (int r = rh*16; r < rh*16 + 16; r++){
    float acc = g_b3f[c] + nf[(r0+r)*FF + c];
    #pragma unroll 16
    for (int k = 0; k < HH; k++) acc += a2s[r*HH+k]*w3s[k*FF+c];
    g_H3[(r0+r)*FF + c] = acc;
  }
}

// ---------------- edge pass 1: GEMM + lrelu, store t to g_T, accumulate stats ----------------
// Pair-tile (bi<=bj) of 32x32 nodes. 256 threads. 16 chunks of 64 edges.
// Micro-tile: 4 edges x 8 cols per thread via 16 packed f32x2 accumulators.
__global__ void __launch_bounds__(256)
k_edge1(const float* __restrict__ W5, const float* __restrict__ b5){
  extern __shared__ float sm[];
  float* W5s = sm;                  // 8192
  float* Hi  = W5s + FF*HH;         // 32*65 = 2080 (padded stride 65)
  float* Hj  = Hi + TI*65;          // 2080
  float* es  = Hj + TI*65;          // 64*64 = 4096
  float* b5s = es + 64*64;          // 128
  float* red = b5s + HH;            // 256
  int tid = threadIdx.x;

  // block -> (bi, bj), bi <= bj
  int p = blockIdx.x, bi = 0, rem = p;
  while (rem >= NB - bi){ rem -= NB - bi; bi++; }
  int bj = bi + rem;

  for (int i = tid; i < FF*HH; i += 256) W5s[i] = W5[i];
  for (int i = tid; i < TI*FF; i += 256){
    int r = i >> 6, k = i & 63;
    Hi[r*65 + k] = g_H3[(bi*TI + r)*FF + k];
    Hj[r*65 + k] = g_H3[(bj*TI + r)*FF + k];
  }
  if (tid < HH) b5s[tid] = b5[tid];
  red[tid] = 0.f;

  int cg = tid & 15;     // col group: cols cg*8 .. cg*8+7
  int eg = tid >> 4;     // edge group: edges 4*eg .. 4*eg+3 (of 64)

  float ss[8], sq[8];
  #pragma unroll
  for (int b = 0; b < 8; b++){ ss[b] = 0.f; sq[b] = 0.f; }
  __syncthreads();

  for (int ii0 = 0; ii0 < TI; ii0 += 2){
    // stage e tile: es[k][m], m in [0,64): edge (ii0+(m>>5), m&31)
    #pragma unroll
    for (int t = 0; t < 16; t++){
      int idx = tid + t*256;
      int m = idx & 63, k = idx >> 6;
      int ii = ii0 + (m >> 5), jj = m & 31;
      es[k*64 + m] = Hi[ii*65 + k] * Hj[jj*65 + k];
    }
    __syncthreads();

    u64 acc[4][4];
    #pragma unroll
    for (int a = 0; a < 4; a++)
      #pragma unroll
      for (int pp = 0; pp < 4; pp++) acc[a][pp] = 0ull;

    const float4* es4 = (const float4*)es;
    #pragma unroll 8
    for (int k = 0; k < FF; k++){
      float4 ev = es4[k*16 + eg];
      ulonglong2 wA = *(const ulonglong2*)(W5s + k*HH + cg*8);
      ulonglong2 wB = *(const ulonglong2*)(W5s + k*HH + cg*8 + 4);
      u64 e0 = pk2(ev.x), e1 = pk2(ev.y), e2 = pk2(ev.z), e3 = pk2(ev.w);
      acc[0][0]=fma2(e0,wA.x,acc[0][0]); acc[0][1]=fma2(e0,wA.y,acc[0][1]);
      acc[0][2]=fma2(e0,wB.x,acc[0][2]); acc[0][3]=fma2(e0,wB.y,acc[0][3]);
      acc[1][0]=fma2(e1,wA.x,acc[1][0]); acc[1][1]=fma2(e1,wA.y,acc[1][1]);
      acc[1][2]=fma2(e1,wB.x,acc[1][2]); acc[1][3]=fma2(e1,wB.y,acc[1][3]);
      acc[2][0]=fma2(e2,wA.x,acc[2][0]); acc[2][1]=fma2(e2,wA.y,acc[2][1]);
      acc[2][2]=fma2(e2,wB.x,acc[2][2]); acc[2][3]=fma2(e2,wB.y,acc[2][3]);
      acc[3][0]=fma2(e3,wA.x,acc[3][0]); acc[3][1]=fma2(e3,wA.y,acc[3][1]);
      acc[3][2]=fma2(e3,wB.x,acc[3][2]); acc[3][3]=fma2(e3,wB.y,acc[3][3]);
    }

    float tv[4][8];
    #pragma unroll
    for (int a = 0; a < 4; a++)
      #pragma unroll
      for (int pp = 0; pp < 4; pp++){
        float2 v = up2(acc[a][pp]);
        tv[a][2*pp]   = lrelu(v.x + b5s[cg*8 + 2*pp]);
        tv[a][2*pp+1] = lrelu(v.y + b5s[cg*8 + 2*pp + 1]);
      }

    // store t rows (all 64 slots, even invalid diag ones) + stats for valid edges
    size_t row_base = (size_t)p*1024 + (size_t)(ii0 >> 1)*64;
    #pragma unroll
    for (int a = 0; a < 4; a++){
      int m = 4*eg + a;
      size_t row = row_base + m;
      g_T[row*32 + cg*2]     = make_float4(tv[a][0], tv[a][1], tv[a][2], tv[a][3]);
      g_T[row*32 + cg*2 + 1] = make_float4(tv[a][4], tv[a][5], tv[a][6], tv[a][7]);
      int ii = ii0 + (m >> 5), jj = m & 31;
      if ((bi < bj) || (jj > ii)){
        #pragma unroll
        for (int b = 0; b < 8; b++){ ss[b] += tv[a][b]; sq[b] += tv[a][b]*tv[a][b]; }
      }
    }
    __syncthreads();
  }

  #pragma unroll
  for (int b = 0; b < 8; b++){
    atomicAdd(&red[cg*8 + b], ss[b]);
    atomicAdd(&red[HH + cg*8 + b], sq[b]);
  }
  __syncthreads();
  if (tid < HH){
    atomicAdd(&g_s5[tid], (double)red[tid]);
    atomicAdd(&g_q5[tid], (double)red[HH + tid]);
  }
}

// ---------------- fold BN5 into W6 ----------------
__global__ void k_fold5(const float* __restrict__ W6, const float* __restrict__ b6,
                        const float* __restrict__ g5, const float* __restrict__ be5){
  __shared__ float bt[HH];
  int tid = threadIdx.x;
  double m = g_s5[tid]/EDGEF;
  double v = g_q5[tid]/EDGEF - m*m;
  float a = rsqrtf((float)v + 1e-5f) * g5[tid];
  bt[tid] = be5[tid] - (float)m*a;
  g_W6f[tid*2]     = a*W6[tid*2];
  g_W6f[tid*2 + 1] = a*W6[tid*2 + 1];
  __syncthreads();
  if (tid < 2){
    float bb = b6[tid];
    for (int k = 0; k < HH; k++) bb += bt[k]*W6[k*2 + tid];
    g_b6f[tid] = bb;
  }
}

// ---------------- edge pass 2: load cached t, folded affine -> 2 logits -> softmax, scatter ----------------
// One thread per edge slot; 4 blocks of 256 per pair-tile (1024 slots).
__global__ void __launch_bounds__(256)
k_edge2(float* __restrict__ out){
  __shared__ float w0s[HH], w1s[HH];
  __shared__ int sb[2];
  int tid = threadIdx.x;
  if (tid < HH){ w0s[tid] = g_W6f[tid*2]; w1s[tid] = g_W6f[tid*2 + 1]; }
  int p = blockIdx.x >> 2;
  if (tid == 0){
    int bi = 0, rem = p;
    while (rem >= NB - bi){ rem -= NB - bi; bi++; }
    sb[0] = bi; sb[1] = bi + rem;
  }
  __syncthreads();
  int bi = sb[0], bj = sb[1];
  int m1024 = ((blockIdx.x & 3) << 8) | tid;
  int chunk = m1024 >> 6, m = m1024 & 63;
  int ii = (chunk << 1) | (m >> 5), jj = m & 31;
  if (bi == bj && jj <= ii) return;   // invalid (diagonal-tile lower half)

  size_t row = (size_t)p*1024 + m1024;
  const float4* tr = g_T + row*32;
  float l0 = g_b6f[0], l1 = g_b6f[1];
  #pragma unroll
  for (int c4 = 0; c4 < 32; c4++){
    float4 v = tr[c4];
    int c = c4*4;
    l0 += v.x*w0s[c] + v.y*w0s[c+1] + v.z*w0s[c+2] + v.w*w0s[c+3];
    l1 += v.x*w1s[c] + v.y*w1s[c+1] + v.z*w1s[c+2] + v.w*w1s[c+3];
  }
  int gi = bi*TI + ii, gj = bj*TI + jj;
  float mx = fmaxf(l0, l1);
  float q0 = __expf(l0 - mx), q1 = __expf(l1 - mx);
  float inv = 1.f/(q0 + q1);
  float2 pr = make_float2(q0*inv, q1*inv);
  float2* o2 = (float2*)out;
  o2[(size_t)gi*NN + gj] = pr;
  o2[(size_t)gj*NN + gi] = pr;
}

// ---------------- launch ----------------
extern "C" void kernel_launch(void* const* d_in, const int* in_sizes, int n_in,
                              void* d_out, int out_size){
  const float* nf  = (const float*)d_in[1];
  const float* W1  = (const float*)d_in[2];
  const float* b1  = (const float*)d_in[3];
  const float* g1  = (const float*)d_in[4];
  const float* be1 = (const float*)d_in[5];
  const float* W2  = (const float*)d_in[6];
  const float* b2  = (const float*)d_in[7];
  const float* g2  = (const float*)d_in[8];
  const float* be2 = (const float*)d_in[9];
  const float* W3  = (const float*)d_in[10];
  const float* b3  = (const float*)d_in[11];
  const float* W5  = (const float*)d_in[12];
  const float* b5  = (const float*)d_in[13];
  const float* g5  = (const float*)d_in[14];
  const float* be5 = (const float*)d_in[15];
  const float* W6  = (const float*)d_in[16];
  const float* b6  = (const float*)d_in[17];
  float* out = (float*)d_out;

  const int EDGE_SMEM = (FF*HH + 2*TI*65 + 64*64 + HH + 2*HH) * 4;   // 67328
  const int N2_SMEM   = (HH*HH + TI*HH) * 4;                          // 81920
  cudaFuncSetAttribute(k_edge1, cudaFuncAttributeMaxDynamicSharedMemorySize, EDGE_SMEM);
  cudaFuncSetAttribute(k_node2, cudaFuncAttributeMaxDynamicSharedMemorySize, N2_SMEM);

  k_init<<<1, 1024>>>(out);
  k_node1<<<NB, 128>>>(nf, W1, b1);
  k_fold1<<<1, 128>>>(W2, b2, g1, be1);
  k_node2<<<NB, 128, N2_SMEM>>>();
  k_fold2<<<1, 128>>>(W3, b3, g2, be2);
  k_node3<<<NB, 128>>>(nf);
  k_edge1<<<NPAIR, 256, EDGE_SMEM>>>(W5, b5);
  k_fold5<<<1, 128>>>(W6, b6, g5, be5);
  k_edge2<<<NPAIR*4, 256>>>(out);
}

// round 4
// speedup vs baseline: 2.6805x; 1.8359x over previous
#include <cuda_runtime.h>
#include <cstdint>

#define NN 2048
#define FF 64
#define HH 128
#define TI 32
#define NB (NN/TI)            // 64
#define NPAIR (NB*(NB+1)/2)   // 2080
#define EDGEF 2096128.0       // NN*(NN-1)/2

typedef unsigned int u32;

// ---------------- scratch ----------------
__device__ float g_A1[NN*HH];
__device__ float g_A2[NN*HH];
__device__ float g_H3[NN*FF];
__device__ float g_W2f[HH*HH];
__device__ float g_b2f[HH];
__device__ float g_W3f[HH*FF];
__device__ float g_b3f[FF];
__device__ float g_W6f[HH*2];
__device__ float g_b6f[2];
__device__ double g_s1[HH], g_q1[HH], g_s2[HH], g_q2[HH], g_s5[HH], g_q5[HH];

__device__ __forceinline__ float lrelu(float x){ return x >= 0.f ? x : 0.01f*x; }
__device__ __forceinline__ u32 cvt_tf32(float x){
  u32 r; asm("cvt.rna.tf32.f32 %0, %1;" : "=r"(r) : "f"(x)); return r;
}

// ---------------- init ----------------
__global__ void k_init(float* __restrict__ out){
  int tid = threadIdx.x;
  if (tid < HH){
    g_s1[tid]=0.0; g_q1[tid]=0.0;
    g_s2[tid]=0.0; g_q2[tid]=0.0;
    g_s5[tid]=0.0; g_q5[tid]=0.0;
  }
  for (int i = tid; i < NN; i += blockDim.x){
    size_t d = (size_t)i*(NN+1)*2;
    out[d] = 0.f; out[d+1] = 0.f;
  }
}

// ---------------- node layer 1 ----------------
__global__ void k_node1(const float* __restrict__ nf, const float* __restrict__ W1,
                        const float* __restrict__ b1){
  __shared__ float nfs[TI*FF];
  int tid = threadIdx.x;
  int r0  = blockIdx.x*TI;
  for (int i = tid; i < TI*FF; i += 128) nfs[i] = nf[r0*FF + i];
  float w[FF];
  #pragma unroll
  for (int k = 0; k < FF; k++) w[k] = W1[k*HH + tid];
  float bc = b1[tid];
  __syncthreads();
  float s = 0.f, q = 0.f;
  for (int r = 0; r < TI; r++){
    float acc = bc;
    #pragma unroll
    for (int k = 0; k < FF; k++) acc += nfs[r*FF+k]*w[k];
    float a = lrelu(acc);
    g_A1[(r0+r)*HH + tid] = a;
    s += a; q += a*a;
  }
  atomicAdd(&g_s1[tid], (double)s);
  atomicAdd(&g_q1[tid], (double)q);
}

__global__ void k_fold1(const float* __restrict__ W2, const float* __restrict__ b2,
                        const float* __restrict__ g1, const float* __restrict__ be1){
  __shared__ float al[HH], bt[HH];
  int tid = threadIdx.x;
  double m = g_s1[tid]/(double)NN;
  double v = g_q1[tid]/(double)NN - m*m;
  float a = rsqrtf((float)v + 1e-5f) * g1[tid];
  al[tid] = a; bt[tid] = be1[tid] - (float)m*a;
  __syncthreads();
  float bb = b2[tid];
  for (int k = 0; k < HH; k++){
    float w = W2[k*HH + tid];
    g_W2f[k*HH + tid] = al[k]*w;
    bb += bt[k]*w;
  }
  g_b2f[tid] = bb;
}

__global__ void k_node2(){
  extern __shared__ float sm2[];
  float* w2s = sm2;
  float* a1s = sm2 + HH*HH;
  int tid = threadIdx.x;
  int r0  = blockIdx.x*TI;
  for (int i = tid; i < HH*HH; i += 128) w2s[i] = g_W2f[i];
  for (int i = tid; i < TI*HH; i += 128) a1s[i] = g_A1[r0*HH + i];
  float bc = g_b2f[tid];
  __syncthreads();
  float s = 0.f, q = 0.f;
  for (int r = 0; r < TI; r++){
    float acc = bc;
    #pragma unroll 16
    for (int k = 0; k < HH; k++) acc += a1s[r*HH+k]*w2s[k*HH+tid];
    float a = lrelu(acc);
    g_A2[(r0+r)*HH + tid] = a;
    s += a; q += a*a;
  }
  atomicAdd(&g_s2[tid], (double)s);
  atomicAdd(&g_q2[tid], (double)q);
}

__global__ void k_fold2(const float* __restrict__ W3, const float* __restrict__ b3,
                        const float* __restrict__ g2, const float* __restrict__ be2){
  __shared__ float al[HH], bt[HH];
  int tid = threadIdx.x;
  double m = g_s2[tid]/(double)NN;
  double v = g_q2[tid]/(double)NN - m*m;
  float a = rsqrtf((float)v + 1e-5f) * g2[tid];
  al[tid] = a; bt[tid] = be2[tid] - (float)m*a;
  __syncthreads();
  if (tid < FF){
    float bb = b3[tid];
    for (int k = 0; k < HH; k++){
      float w = W3[k*FF + tid];
      g_W3f[k*FF + tid] = al[k]*w;
      bb += bt[k]*w;
    }
    g_b3f[tid] = bb;
  }
}

__global__ void k_node3(const float* __restrict__ nf){
  __shared__ float a2s[TI*HH];
  __shared__ float w3s[HH*FF];
  int tid = threadIdx.x;
  int r0  = blockIdx.x*TI;
  for (int i = tid; i < TI*HH; i += 128) a2s[i] = g_A2[r0*HH + i];
  for (int i = tid; i < HH*FF; i += 128) w3s[i] = g_W3f[i];
  __syncthreads();
  int c = tid & 63, rh = tid >> 6;
  for (int r = rh*16; r < rh*16 + 16; r++){
    float acc = g_b3f[c] + nf[(r0+r)*FF + c];
    #pragma unroll 16
    for (int k = 0; k < HH; k++) acc += a2s[r*HH+k]*w3s[k*FF+c];
    g_H3[(r0+r)*FF + c] = acc;
  }
}

// ---------------- fold BN5 into W6 ----------------
__global__ void k_fold5(const float* __restrict__ W6, const float* __restrict__ b6,
                        const float* __restrict__ g5, const float* __restrict__ be5){
  __shared__ float bt[HH];
  int tid = threadIdx.x;
  double m = g_s5[tid]/EDGEF;
  double v = g_q5[tid]/EDGEF - m*m;
  float a = rsqrtf((float)v + 1e-5f) * g5[tid];
  bt[tid] = be5[tid] - (float)m*a;
  g_W6f[tid*2]     = a*W6[tid*2];
  g_W6f[tid*2 + 1] = a*W6[tid*2 + 1];
  __syncthreads();
  if (tid < 2){
    float bb = b6[tid];
    for (int k = 0; k < HH; k++) bb += bt[k]*W6[k*2 + tid];
    g_b6f[tid] = bb;
  }
}

// ---------------- edge kernel via mma.sync tf32 ----------------
// SMEM floats: W5s 64x136=8704 | Hi 32x68=2176 | Hj 2176 | b5s 128 | w6s 256 | red 256
#define W5S_STR 136
#define H_STR   68
#define EDGE_SMEM ((8704 + 2176 + 2176 + 128 + 256 + 256)*4)

template<int PASS>
__global__ void __launch_bounds__(256)
k_edgeM(const float* __restrict__ W5, const float* __restrict__ b5,
        float* __restrict__ out){
  extern __shared__ float sm[];
  float* W5s = sm;
  float* Hi  = sm + 8704;
  float* Hj  = Hi + 2176;
  float* b5s = Hj + 2176;
  float* w6s = b5s + 128;
  float* red = w6s + 256;

  int tid = threadIdx.x;
  int lane = tid & 31, wid = tid >> 5;
  int mg = wid & 3, ng = wid >> 2;
  int qid = lane >> 2, qlane = lane & 3;

  int p = blockIdx.x, bi = 0, rem = p;
  while (rem >= NB - bi){ rem -= NB - bi; bi++; }
  int bj = bi + rem;

  // stage W5 as tf32, Hi/Hj, biases
  for (int i = tid; i < FF*HH; i += 256){
    int k = i >> 7, n = i & 127;
    W5s[k*W5S_STR + n] = __uint_as_float(cvt_tf32(W5[i]));
  }
  for (int i = tid; i < TI*FF; i += 256){
    int r = i >> 6, k = i & 63;
    Hi[r*H_STR + k] = g_H3[(bi*TI + r)*FF + k];
    Hj[r*H_STR + k] = g_H3[(bj*TI + r)*FF + k];
  }
  if (tid < HH) b5s[tid] = b5[tid];
  if (PASS == 2 && tid < HH){ w6s[tid] = g_W6f[tid*2]; w6s[HH + tid] = g_W6f[tid*2+1]; }
  red[tid] = 0.f;
  float b60 = 0.f, b61 = 0.f;
  if (PASS == 2){ b60 = g_b6f[0]; b61 = g_b6f[1]; }
  __syncthreads();

  float ss[16], sq[16];
  if (PASS == 1){
    #pragma unroll
    for (int i = 0; i < 16; i++){ ss[i] = 0.f; sq[i] = 0.f; }
  }

  for (int t = 0; t < 8; t++){
    float acc[2][8][4];
    #pragma unroll
    for (int mt = 0; mt < 2; mt++)
      #pragma unroll
      for (int nt = 0; nt < 8; nt++)
        #pragma unroll
        for (int c = 0; c < 4; c++) acc[mt][nt][c] = 0.f;

    int ii = t*4 + mg;
    const float* HiRow = Hi + ii*H_STR;

    #pragma unroll
    for (int ks = 0; ks < 8; ks++){
      int k0 = ks*8 + qlane;
      u32 bf0[8], bf1[8];
      #pragma unroll
      for (int nt = 0; nt < 8; nt++){
        int n = ng*64 + nt*8 + qid;
        bf0[nt] = __float_as_uint(W5s[k0*W5S_STR + n]);
        bf1[nt] = __float_as_uint(W5s[(k0+4)*W5S_STR + n]);
      }
      float hi0 = HiRow[k0], hi1 = HiRow[k0+4];
      #pragma unroll
      for (int mt = 0; mt < 2; mt++){
        int jA = mt*16 + qid;
        float hA0 = Hj[jA*H_STR + k0],     hA1 = Hj[jA*H_STR + k0 + 4];
        float hB0 = Hj[(jA+8)*H_STR + k0], hB1 = Hj[(jA+8)*H_STR + k0 + 4];
        u32 a0 = cvt_tf32(hi0*hA0);
        u32 a1 = cvt_tf32(hi0*hB0);
        u32 a2 = cvt_tf32(hi1*hA1);
        u32 a3 = cvt_tf32(hi1*hB1);
        #pragma unroll
        for (int nt = 0; nt < 8; nt++){
          asm volatile(
            "mma.sync.aligned.m16n8k8.row.col.f32.tf32.tf32.f32 "
            "{%0,%1,%2,%3},{%4,%5,%6,%7},{%8,%9},{%0,%1,%2,%3};"
            : "+f"(acc[mt][nt][0]), "+f"(acc[mt][nt][1]),
              "+f"(acc[mt][nt][2]), "+f"(acc[mt][nt][3])
            : "r"(a0),"r"(a1),"r"(a2),"r"(a3), "r"(bf0[nt]),"r"(bf1[nt]));
        }
      }
    }

    // ---- epilogue for tile t ----
    if (PASS == 1){
      float b5v[16];
      #pragma unroll
      for (int i = 0; i < 16; i++)
        b5v[i] = b5s[ng*64 + (i>>1)*8 + qlane*2 + (i&1)];
      #pragma unroll
      for (int mt = 0; mt < 2; mt++)
        #pragma unroll
        for (int nt = 0; nt < 8; nt++)
          #pragma unroll
          for (int c = 0; c < 4; c++){
            int jj = mt*16 + qid + (c>>1)*8;
            float tv = lrelu(acc[mt][nt][c] + b5v[nt*2 + (c&1)]);
            if ((bi < bj) || (jj > ii)){
              ss[nt*2+(c&1)] += tv; sq[nt*2+(c&1)] += tv*tv;
            }
          }
    } else {
      float b5v[16], w0v[16], w1v[16];
      #pragma unroll
      for (int i = 0; i < 16; i++){
        int col = ng*64 + (i>>1)*8 + qlane*2 + (i&1);
        b5v[i] = b5s[col]; w0v[i] = w6s[col]; w1v[i] = w6s[HH + col];
      }
      float p0[4], p1[4];
      #pragma unroll
      for (int i = 0; i < 4; i++){ p0[i] = 0.f; p1[i] = 0.f; }
      #pragma unroll
      for (int mt = 0; mt < 2; mt++)
        #pragma unroll
        for (int nt = 0; nt < 8; nt++)
          #pragma unroll
          for (int c = 0; c < 4; c++){
            float tv = lrelu(acc[mt][nt][c] + b5v[nt*2 + (c&1)]);
            int idx = mt*2 + (c>>1);
            p0[idx] += tv * w0v[nt*2 + (c&1)];
            p1[idx] += tv * w1v[nt*2 + (c&1)];
          }
      #pragma unroll
      for (int i = 0; i < 4; i++){
        p0[i] += __shfl_xor_sync(0xffffffffu, p0[i], 1);
        p0[i] += __shfl_xor_sync(0xffffffffu, p0[i], 2);
        p1[i] += __shfl_xor_sync(0xffffffffu, p1[i], 1);
        p1[i] += __shfl_xor_sync(0xffffffffu, p1[i], 2);
      }
      if (qlane == 0){
        #pragma unroll
        for (int i = 0; i < 4; i++){
          int row = mg*32 + (i>>1)*16 + qid + (i&1)*8;   // i = mt*2 + h
          atomicAdd(&red[row], p0[i]);
          atomicAdd(&red[HH + row], p1[i]);
        }
      }
      __syncthreads();
      if (tid < 128){
        int row = tid;
        int jj = row & 31, iiw = t*4 + (row >> 5);
        if ((bi < bj) || (jj > iiw)){
          float l0 = red[row] + b60, l1 = red[HH + row] + b61;
          int gi = bi*TI + iiw, gj = bj*TI + jj;
          float mx = fmaxf(l0, l1);
          float q0 = __expf(l0 - mx), q1 = __expf(l1 - mx);
          float inv = 1.f/(q0 + q1);
          float2 pr = make_float2(q0*inv, q1*inv);
          float2* o2 = (float2*)out;
          o2[(size_t)gi*NN + gj] = pr;
          o2[(size_t)gj*NN + gi] = pr;
        }
      }
      __syncthreads();
      red[tid] = 0.f;           // clear rowbuf for next tile
      __syncthreads();
    }
  }

  if (PASS == 1){
    #pragma unroll
    for (int i = 0; i < 16; i++){
      int col = ng*64 + (i>>1)*8 + qlane*2 + (i&1);
      atomicAdd(&red[col], ss[i]);
      atomicAdd(&red[HH + col], sq[i]);
    }
    __syncthreads();
    if (tid < 128){
      atomicAdd(&g_s5[tid], (double)red[tid]);
      atomicAdd(&g_q5[tid], (double)red[HH + tid]);
    }
  }
}

// ---------------- launch ----------------
extern "C" void kernel_launch(void* const* d_in, const int* in_sizes, int n_in,
                              void* d_out, int out_size){
  const float* nf  = (const float*)d_in[1];
  const float* W1  = (const float*)d_in[2];
  const float* b1  = (const float*)d_in[3];
  const float* g1  = (const float*)d_in[4];
  const float* be1 = (const float*)d_in[5];
  const float* W2  = (const float*)d_in[6];
  const float* b2  = (const float*)d_in[7];
  const float* g2  = (const float*)d_in[8];
  const float* be2 = (const float*)d_in[9];
  const float* W3  = (const float*)d_in[10];
  const float* b3  = (const float*)d_in[11];
  const float* W5  = (const float*)d_in[12];
  const float* b5  = (const float*)d_in[13];
  const float* g5  = (const float*)d_in[14];
  const float* be5 = (const float*)d_in[15];
  const float* W6  = (const float*)d_in[16];
  const float* b6  = (const float*)d_in[17];
  float* out = (float*)d_out;

  const int N2_SMEM = (HH*HH + TI*HH) * 4;
  cudaFuncSetAttribute(k_node2, cudaFuncAttributeMaxDynamicSharedMemorySize, N2_SMEM);
  cudaFuncSetAttribute(k_edgeM<1>, cudaFuncAttributeMaxDynamicSharedMemorySize, EDGE_SMEM);
  cudaFuncSetAttribute(k_edgeM<2>, cudaFuncAttributeMaxDynamicSharedMemorySize, EDGE_SMEM);

  k_init<<<1, 1024>>>(out);
  k_node1<<<NB, 128>>>(nf, W1, b1);
  k_fold1<<<1, 128>>>(W2, b2, g1, be1);
  k_node2<<<NB, 128, N2_SMEM>>>();
  k_fold2<<<1, 128>>>(W3, b3, g2, be2);
  k_node3<<<NB, 128>>>(nf);
  k_edgeM<1><<<NPAIR, 256, EDGE_SMEM>>>(W5, b5, out);
  k_fold5<<<1, 128>>>(W6, b6, g5, be5);
  k_edgeM<2><<<NPAIR, 256, EDGE_SMEM>>>(W5, b5, out);
}

// round 5
// speedup vs baseline: 2.8628x; 1.0680x over previous
#include <cuda_runtime.h>
#include <cuda_fp16.h>
#include <cstdint>

#define NN 2048
#define FF 64
#define HH 128
#define TI 32
#define NB (NN/TI)            // 64
#define NPAIR (NB*(NB+1)/2)   // 2080
#define EDGEF 2096128.0       // NN*(NN-1)/2
#define ES ((size_t)NPAIR*1024)   // 2,129,920 edge slots

typedef unsigned int u32;

// ---------------- scratch ----------------
__device__ float g_A1[NN*HH];
__device__ float g_A2[NN*HH];
__device__ float g_H3[NN*FF];
__device__ float g_W2f[HH*HH];
__device__ float g_b2f[HH];
__device__ float g_W3f[HH*FF];
__device__ float g_b3f[FF];
__device__ float g_W6f[HH*2];
__device__ float g_b6f[2];
__device__ double g_s1[HH], g_q1[HH], g_s2[HH], g_q2[HH], g_s5[HH], g_q5[HH];
// t-cache, column-planar: g_Tc[c2*ES + edge_slot], half2 per u32. 545 MB.
__device__ u32 g_Tc[64*ES];

__device__ __forceinline__ float lrelu(float x){ return x >= 0.f ? x : 0.01f*x; }
__device__ __forceinline__ u32 cvt_tf32(float x){
  u32 r; asm("cvt.rna.tf32.f32 %0, %1;" : "=r"(r) : "f"(x)); return r;
}

// ---------------- init ----------------
__global__ void k_init(float* __restrict__ out){
  int tid = threadIdx.x;
  if (tid < HH){
    g_s1[tid]=0.0; g_q1[tid]=0.0;
    g_s2[tid]=0.0; g_q2[tid]=0.0;
    g_s5[tid]=0.0; g_q5[tid]=0.0;
  }
  for (int i = tid; i < NN; i += blockDim.x){
    size_t d = (size_t)i*(NN+1)*2;
    out[d] = 0.f; out[d+1] = 0.f;
  }
}

// ---------------- node layer 1: 128 blocks x 16 rows ----------------
__global__ void k_node1(const float* __restrict__ nf, const float* __restrict__ W1,
                        const float* __restrict__ b1){
  __shared__ float nfs[16*FF];
  int tid = threadIdx.x;
  int r0  = blockIdx.x*16;
  for (int i = tid; i < 16*FF; i += 128) nfs[i] = nf[r0*FF + i];
  float w[FF];
  #pragma unroll
  for (int k = 0; k < FF; k++) w[k] = W1[k*HH + tid];
  float bc = b1[tid];
  __syncthreads();
  float s = 0.f, q = 0.f;
  for (int r = 0; r < 16; r++){
    float acc = bc;
    #pragma unroll
    for (int k = 0; k < FF; k++) acc += nfs[r*FF+k]*w[k];
    float a = lrelu(acc);
    g_A1[(r0+r)*HH + tid] = a;
    s += a; q += a*a;
  }
  atomicAdd(&g_s1[tid], (double)s);
  atomicAdd(&g_q1[tid], (double)q);
}

__global__ void k_fold1(const float* __restrict__ W2, const float* __restrict__ b2,
                        const float* __restrict__ g1, const float* __restrict__ be1){
  __shared__ float al[HH], bt[HH];
  int tid = threadIdx.x;
  double m = g_s1[tid]/(double)NN;
  double v = g_q1[tid]/(double)NN - m*m;
  float a = rsqrtf((float)v + 1e-5f) * g1[tid];
  al[tid] = a; bt[tid] = be1[tid] - (float)m*a;
  __syncthreads();
  float bb = b2[tid];
  for (int k = 0; k < HH; k++){
    float w = W2[k*HH + tid];
    g_W2f[k*HH + tid] = al[k]*w;
    bb += bt[k]*w;
  }
  g_b2f[tid] = bb;
}

// ---------------- node layer 2: 128 blocks x 16 rows ----------------
__global__ void k_node2(){
  extern __shared__ float sm2[];
  float* w2s = sm2;                 // 16384
  float* a1s = sm2 + HH*HH;         // 2048
  int tid = threadIdx.x;
  int r0  = blockIdx.x*16;
  for (int i = tid; i < HH*HH; i += 128) w2s[i] = g_W2f[i];
  for (int i = tid; i < 16*HH; i += 128) a1s[i] = g_A1[r0*HH + i];
  float bc = g_b2f[tid];
  __syncthreads();
  float s = 0.f, q = 0.f;
  for (int r = 0; r < 16; r++){
    float acc = bc;
    #pragma unroll 16
    for (int k = 0; k < HH; k++) acc += a1s[r*HH+k]*w2s[k*HH+tid];
    float a = lrelu(acc);
    g_A2[(r0+r)*HH + tid] = a;
    s += a; q += a*a;
  }
  atomicAdd(&g_s2[tid], (double)s);
  atomicAdd(&g_q2[tid], (double)q);
}

__global__ void k_fold2(const float* __restrict__ W3, const float* __restrict__ b3,
                        const float* __restrict__ g2, const float* __restrict__ be2){
  __shared__ float al[HH], bt[HH];
  int tid = threadIdx.x;
  double m = g_s2[tid]/(double)NN;
  double v = g_q2[tid]/(double)NN - m*m;
  float a = rsqrtf((float)v + 1e-5f) * g2[tid];
  al[tid] = a; bt[tid] = be2[tid] - (float)m*a;
  __syncthreads();
  if (tid < FF){
    float bb = b3[tid];
    for (int k = 0; k < HH; k++){
      float w = W3[k*FF + tid];
      g_W3f[k*FF + tid] = al[k]*w;
      bb += bt[k]*w;
    }
    g_b3f[tid] = bb;
  }
}

// ---------------- node layer 3: 128 blocks x 16 rows ----------------
__global__ void k_node3(const float* __restrict__ nf){
  __shared__ float a2s[16*HH];    // 8KB
  __shared__ float w3s[HH*FF];    // 32KB
  int tid = threadIdx.x;
  int r0  = blockIdx.x*16;
  for (int i = tid; i < 16*HH; i += 128) a2s[i] = g_A2[r0*HH + i];
  for (int i = tid; i < HH*FF; i += 128) w3s[i] = g_W3f[i];
  __syncthreads();
  int c = tid & 63, rh = tid >> 6;
  for (int r = rh*8; r < rh*8 + 8; r++){
    float acc = g_b3f[c] + nf[(r0+r)*FF + c];
    #pragma unroll 16
    for (int k = 0; k < HH; k++) acc += a2s[r*HH+k]*w3s[k*FF+c];
    g_H3[(r0+r)*FF + c] = acc;
  }
}

// ---------------- fold BN5 into W6 ----------------
__global__ void k_fold5(const float* __restrict__ W6, const float* __restrict__ b6,
                        const float* __restrict__ g5, const float* __restrict__ be5){
  __shared__ float bt[HH];
  int tid = threadIdx.x;
  double m = g_s5[tid]/EDGEF;
  double v = g_q5[tid]/EDGEF - m*m;
  float a = rsqrtf((float)v + 1e-5f) * g5[tid];
  bt[tid] = be5[tid] - (float)m*a;
  g_W6f[tid*2]     = a*W6[tid*2];
  g_W6f[tid*2 + 1] = a*W6[tid*2 + 1];
  __syncthreads();
  if (tid < 2){
    float bb = b6[tid];
    for (int k = 0; k < HH; k++) bb += bt[k]*W6[k*2 + tid];
    g_b6f[tid] = bb;
  }
}

// ---------------- edge pass 1: tf32 mma.sync GEMM + stats + fp16 t store ----------------
// SMEM floats: W5v 64x132=8448 | Hi 32x68=2176 | Hj 2176 | b5s 128 | red 256 | stage 8320(u32)
#define W5V_STR 132
#define H_STR   68
#define OFF_HI  8448
#define OFF_HJ  (OFF_HI+2176)
#define OFF_B5  (OFF_HJ+2176)
#define OFF_RED (OFF_B5+128)
#define OFF_ST  (OFF_RED+256)
#define EDGE1_SMEM ((OFF_ST + 8320)*4)   // 86016 bytes

__global__ void __launch_bounds__(256)
k_edgeG(const float* __restrict__ W5, const float* __restrict__ b5){
  extern __shared__ float sm[];
  float* W5v = sm;
  float* Hi  = sm + OFF_HI;
  float* Hj  = sm + OFF_HJ;
  float* b5s = sm + OFF_B5;
  float* red = sm + OFF_RED;
  u32*   st  = (u32*)(sm + OFF_ST);

  int tid = threadIdx.x;
  int lane = tid & 31, wid = tid >> 5;
  int mg = wid & 3, ng = wid >> 2;
  int qid = lane >> 2, qlane = lane & 3;

  int p = blockIdx.x, bi = 0, rem = p;
  while (rem >= NB - bi){ rem -= NB - bi; bi++; }
  int bj = bi + rem;

  // stage W5 in tf32 fragment-order layout: W5v[k*132 + ng*64 + qid*8 + nt],
  // source col n = ng*64 + nt*8 + qid
  for (int i = tid; i < FF*HH; i += 256){
    int k = i >> 7, f = i & 127;
    int n = ((f>>6)<<6) + ((f&7)<<3) + ((f>>3)&7);
    W5v[k*W5V_STR + f] = __uint_as_float(cvt_tf32(W5[k*HH + n]));
  }
  for (int i = tid; i < TI*FF; i += 256){
    int r = i >> 6, k = i & 63;
    Hi[r*H_STR + k] = g_H3[(bi*TI + r)*FF + k];
    Hj[r*H_STR + k] = g_H3[(bj*TI + r)*FF + k];
  }
  if (tid < HH) b5s[tid] = b5[tid];
  red[tid] = 0.f;
  __syncthreads();

  float ss[16], sq[16];
  #pragma unroll
  for (int i = 0; i < 16; i++){ ss[i] = 0.f; sq[i] = 0.f; }

  for (int t = 0; t < 8; t++){
    float acc[2][8][4];
    #pragma unroll
    for (int mt = 0; mt < 2; mt++)
      #pragma unroll
      for (int nt = 0; nt < 8; nt++)
        #pragma unroll
        for (int c = 0; c < 4; c++) acc[mt][nt][c] = 0.f;

    int ii = t*4 + mg;
    const float* HiRow = Hi + ii*H_STR;

    #pragma unroll
    for (int ks = 0; ks < 8; ks++){
      int k0 = ks*8 + qlane;
      const float4* Bv0 = (const float4*)(W5v + k0*W5V_STR + ng*64 + qid*8);
      const float4* Bv1 = (const float4*)(W5v + (k0+4)*W5V_STR + ng*64 + qid*8);
      float4 b0a = Bv0[0], b0b = Bv0[1];
      float4 b1a = Bv1[0], b1b = Bv1[1];
      u32 bf0[8], bf1[8];
      bf0[0]=__float_as_uint(b0a.x); bf0[1]=__float_as_uint(b0a.y);
      bf0[2]=__float_as_uint(b0a.z); bf0[3]=__float_as_uint(b0a.w);
      bf0[4]=__float_as_uint(b0b.x); bf0[5]=__float_as_uint(b0b.y);
      bf0[6]=__float_as_uint(b0b.z); bf0[7]=__float_as_uint(b0b.w);
      bf1[0]=__float_as_uint(b1a.x); bf1[1]=__float_as_uint(b1a.y);
      bf1[2]=__float_as_uint(b1a.z); bf1[3]=__float_as_uint(b1a.w);
      bf1[4]=__float_as_uint(b1b.x); bf1[5]=__float_as_uint(b1b.y);
      bf1[6]=__float_as_uint(b1b.z); bf1[7]=__float_as_uint(b1b.w);

      float hi0 = HiRow[k0], hi1 = HiRow[k0+4];
      #pragma unroll
      for (int mt = 0; mt < 2; mt++){
        int jA = mt*16 + qid;
        float hA0 = Hj[jA*H_STR + k0],     hA1 = Hj[jA*H_STR + k0 + 4];
        float hB0 = Hj[(jA+8)*H_STR + k0], hB1 = Hj[(jA+8)*H_STR + k0 + 4];
        u32 a0 = cvt_tf32(hi0*hA0);
        u32 a1 = cvt_tf32(hi0*hB0);
        u32 a2 = cvt_tf32(hi1*hA1);
        u32 a3 = cvt_tf32(hi1*hB1);
        #pragma unroll
        for (int nt = 0; nt < 8; nt++){
          asm volatile(
            "mma.sync.aligned.m16n8k8.row.col.f32.tf32.tf32.f32 "
            "{%0,%1,%2,%3},{%4,%5,%6,%7},{%8,%9},{%0,%1,%2,%3};"
            : "+f"(acc[mt][nt][0]), "+f"(acc[mt][nt][1]),
              "+f"(acc[mt][nt][2]), "+f"(acc[mt][nt][3])
            : "r"(a0),"r"(a1),"r"(a2),"r"(a3), "r"(bf0[nt]),"r"(bf1[nt]));
        }
      }
    }

    // epilogue: lrelu + bias, stats, pack fp16 into stage
    float b5v[16];
    #pragma unroll
    for (int i = 0; i < 16; i++)
      b5v[i] = b5s[ng*64 + (i>>1)*8 + qlane*2 + (i&1)];

    #pragma unroll
    for (int mt = 0; mt < 2; mt++)
      #pragma unroll
      for (int nt = 0; nt < 8; nt++)
        #pragma unroll
        for (int h = 0; h < 2; h++){
          float tv0 = lrelu(acc[mt][nt][2*h]   + b5v[nt*2]);
          float tv1 = lrelu(acc[mt][nt][2*h+1] + b5v[nt*2+1]);
          int jj = mt*16 + qid + h*8;
          if ((bi < bj) || (jj > ii)){
            ss[nt*2]   += tv0; sq[nt*2]   += tv0*tv0;
            ss[nt*2+1] += tv1; sq[nt*2+1] += tv1*tv1;
          }
          int r  = mg*32 + jj;                 // row within this 128-slot tile
          int c2 = ng*32 + nt*4 + qlane;       // half2 column
          __half2 hv = __floats2half2_rn(tv0, tv1);
          st[r*65 + c2] = *(u32*)&hv;
        }
    __syncthreads();

    // coalesced write of stage -> column-planar t-cache
    size_t slotbase = (size_t)p*1024 + (size_t)t*128;
    #pragma unroll 8
    for (int i = tid; i < 8192; i += 256){
      int c2 = i >> 7, r = i & 127;
      g_Tc[(size_t)c2*ES + slotbase + r] = st[r*65 + c2];
    }
    __syncthreads();
  }

  #pragma unroll
  for (int i = 0; i < 16; i++){
    int col = ng*64 + (i>>1)*8 + qlane*2 + (i&1);
    atomicAdd(&red[col], ss[i]);
    atomicAdd(&red[HH + col], sq[i]);
  }
  __syncthreads();
  if (tid < 128){
    atomicAdd(&g_s5[tid], (double)red[tid]);
    atomicAdd(&g_q5[tid], (double)red[HH + tid]);
  }
}

// ---------------- edge pass 2: stream t-cache, folded projection -> softmax -> scatter ----------------
__global__ void __launch_bounds__(256)
k_edge2h(float* __restrict__ out){
  __shared__ float w0s[HH], w1s[HH];
  __shared__ int sbb[2];
  int tid = threadIdx.x;
  if (tid < HH){ w0s[tid] = g_W6f[tid*2]; w1s[tid] = g_W6f[tid*2 + 1]; }
  int p = blockIdx.x >> 2;
  if (tid == 0){
    int bi = 0, rem = p;
    while (rem >= NB - bi){ rem -= NB - bi; bi++; }
    sbb[0] = bi; sbb[1] = bi + rem;
  }
  __syncthreads();
  int bi = sbb[0], bj = sbb[1];
  int slot = ((blockIdx.x & 3) << 8) | tid;
  int ii = slot >> 5, jj = slot & 31;
  if (bi == bj && jj <= ii) return;

  size_t base = (size_t)p*1024 + slot;
  float l0 = g_b6f[0], l1 = g_b6f[1];
  #pragma unroll 8
  for (int c2 = 0; c2 < 64; c2++){
    u32 v = g_Tc[(size_t)c2*ES + base];
    float2 f = __half22float2(*(__half2*)&v);
    l0 += f.x*w0s[2*c2] + f.y*w0s[2*c2+1];
    l1 += f.x*w1s[2*c2] + f.y*w1s[2*c2+1];
  }
  int gi = bi*TI + ii, gj = bj*TI + jj;
  float mx = fmaxf(l0, l1);
  float q0 = __expf(l0 - mx), q1 = __expf(l1 - mx);
  float inv = 1.f/(q0 + q1);
  float2 pr = make_float2(q0*inv, q1*inv);
  float2* o2 = (float2*)out;
  o2[(size_t)gi*NN + gj] = pr;
  o2[(size_t)gj*NN + gi] = pr;
}

// ---------------- launch ----------------
extern "C" void kernel_launch(void* const* d_in, const int* in_sizes, int n_in,
                              void* d_out, int out_size){
  const float* nf  = (const float*)d_in[1];
  const float* W1  = (const float*)d_in[2];
  const float* b1  = (const float*)d_in[3];
  const float* g1  = (const float*)d_in[4];
  const float* be1 = (const float*)d_in[5];
  const float* W2  = (const float*)d_in[6];
  const float* b2  = (const float*)d_in[7];
  const float* g2  = (const float*)d_in[8];
  const float* be2 = (const float*)d_in[9];
  const float* W3  = (const float*)d_in[10];
  const float* b3  = (const float*)d_in[11];
  const float* W5  = (const float*)d_in[12];
  const float* b5  = (const float*)d_in[13];
  const float* g5  = (const float*)d_in[14];
  const float* be5 = (const float*)d_in[15];
  const float* W6  = (const float*)d_in[16];
  const float* b6  = (const float*)d_in[17];
  float* out = (float*)d_out;

  const int N2_SMEM = (HH*HH + 16*HH) * 4;
  cudaFuncSetAttribute(k_node2, cudaFuncAttributeMaxDynamicSharedMemorySize, N2_SMEM);
  cudaFuncSetAttribute(k_edgeG, cudaFuncAttributeMaxDynamicSharedMemorySize, EDGE1_SMEM);

  k_init<<<1, 1024>>>(out);
  k_node1<<<128, 128>>>(nf, W1, b1);
  k_fold1<<<1, 128>>>(W2, b2, g1, be1);
  k_node2<<<128, 128, N2_SMEM>>>();
  k_fold2<<<1, 128>>>(W3, b3, g2, be2);
  k_node3<<<128, 128>>>(nf);
  k_edgeG<<<NPAIR, 256, EDGE1_SMEM>>>(W5, b5);
  k_fold5<<<1, 128>>>(W6, b6, g5, be5);
  k_edge2h<<<NPAIR*4, 256>>>(out);
}

// round 6
// speedup vs baseline: 3.1865x; 1.1130x over previous
#include <cuda_runtime.h>
#include <cuda_fp16.h>
#include <cstdint>

#define NN 2048
#define FF 64
#define HH 128
#define TI 32
#define NB (NN/TI)            // 64
#define NPAIR (NB*(NB+1)/2)   // 2080
#define EDGEF 2096128.0       // NN*(NN-1)/2
#define ES ((size_t)NPAIR*1024)   // 2,129,920 edge slots

typedef unsigned int u32;

// ---------------- scratch ----------------
__device__ float g_A1[NN*HH];
__device__ float g_A2[NN*HH];
__device__ float g_H3[NN*FF];
__device__ float g_W2f[HH*HH];
__device__ float g_b2f[HH];
__device__ float g_W3f[HH*FF];
__device__ float g_b3f[FF];
__device__ float g_W6f[HH*2];
__device__ float g_b6f[2];
__device__ double g_s1[HH], g_q1[HH], g_s2[HH], g_q2[HH], g_s5[HH], g_q5[HH];
// t-cache, column-planar: g_Tc[c2*ES + edge_slot], half2 per u32. 545 MB.
__device__ u32 g_Tc[64*ES];

__device__ __forceinline__ float lrelu(float x){ return x >= 0.f ? x : 0.01f*x; }

// ---------------- init ----------------
__global__ void k_init(float* __restrict__ out){
  int tid = threadIdx.x;
  if (tid < HH){
    g_s1[tid]=0.0; g_q1[tid]=0.0;
    g_s2[tid]=0.0; g_q2[tid]=0.0;
    g_s5[tid]=0.0; g_q5[tid]=0.0;
  }
  for (int i = tid; i < NN; i += blockDim.x){
    size_t d = (size_t)i*(NN+1)*2;
    out[d] = 0.f; out[d+1] = 0.f;
  }
}

// ---------------- node layer 1: 128 blocks x 16 rows, 4-chain ILP ----------------
__global__ void k_node1(const float* __restrict__ nf, const float* __restrict__ W1,
                        const float* __restrict__ b1){
  __shared__ float nfs[16*FF];
  int tid = threadIdx.x;
  int r0  = blockIdx.x*16;
  for (int i = tid; i < 16*FF; i += 128) nfs[i] = nf[r0*FF + i];
  float w[FF];
  #pragma unroll
  for (int k = 0; k < FF; k++) w[k] = W1[k*HH + tid];
  float bc = b1[tid];
  __syncthreads();
  float s = 0.f, q = 0.f;
  for (int r = 0; r < 16; r++){
    float a0=0.f, a1=0.f, a2=0.f, a3=0.f;
    #pragma unroll
    for (int k = 0; k < FF; k += 4){
      a0 += nfs[r*FF+k]*w[k];
      a1 += nfs[r*FF+k+1]*w[k+1];
      a2 += nfs[r*FF+k+2]*w[k+2];
      a3 += nfs[r*FF+k+3]*w[k+3];
    }
    float a = lrelu(bc + (a0+a1) + (a2+a3));
    g_A1[(r0+r)*HH + tid] = a;
    s += a; q += a*a;
  }
  atomicAdd(&g_s1[tid], (double)s);
  atomicAdd(&g_q1[tid], (double)q);
}

__global__ void k_fold1(const float* __restrict__ W2, const float* __restrict__ b2,
                        const float* __restrict__ g1, const float* __restrict__ be1){
  __shared__ float al[HH], bt[HH];
  int tid = threadIdx.x;
  double m = g_s1[tid]/(double)NN;
  double v = g_q1[tid]/(double)NN - m*m;
  float a = rsqrtf((float)v + 1e-5f) * g1[tid];
  al[tid] = a; bt[tid] = be1[tid] - (float)m*a;
  __syncthreads();
  float bb = b2[tid];
  for (int k = 0; k < HH; k++){
    float w = W2[k*HH + tid];
    g_W2f[k*HH + tid] = al[k]*w;
    bb += bt[k]*w;
  }
  g_b2f[tid] = bb;
}

// ---------------- node layer 2: 16 row-accumulators, 8-wide k blocks ----------------
__global__ void k_node2(){
  extern __shared__ float sm2[];
  float* w2s = sm2;                 // 16384
  float* a1s = sm2 + HH*HH;         // 2048
  int tid = threadIdx.x;
  int r0  = blockIdx.x*16;
  for (int i = tid; i < HH*HH; i += 128) w2s[i] = g_W2f[i];
  for (int i = tid; i < 16*HH; i += 128) a1s[i] = g_A1[r0*HH + i];
  float bc = g_b2f[tid];
  __syncthreads();
  float acc[16];
  #pragma unroll
  for (int r = 0; r < 16; r++) acc[r] = 0.f;
  for (int kb = 0; kb < HH; kb += 8){
    float w0 = w2s[(kb+0)*HH+tid], w1 = w2s[(kb+1)*HH+tid];
    float w2 = w2s[(kb+2)*HH+tid], w3 = w2s[(kb+3)*HH+tid];
    float w4 = w2s[(kb+4)*HH+tid], w5 = w2s[(kb+5)*HH+tid];
    float w6 = w2s[(kb+6)*HH+tid], w7 = w2s[(kb+7)*HH+tid];
    #pragma unroll
    for (int r = 0; r < 16; r++){
      const float* ar = a1s + r*HH + kb;
      float p0 = ar[0]*w0 + ar[1]*w1;
      float p1 = ar[2]*w2 + ar[3]*w3;
      float p2 = ar[4]*w4 + ar[5]*w5;
      float p3 = ar[6]*w6 + ar[7]*w7;
      acc[r] += (p0+p1) + (p2+p3);
    }
  }
  float s = 0.f, q = 0.f;
  #pragma unroll
  for (int r = 0; r < 16; r++){
    float a = lrelu(acc[r] + bc);
    g_A2[(r0+r)*HH + tid] = a;
    s += a; q += a*a;
  }
  atomicAdd(&g_s2[tid], (double)s);
  atomicAdd(&g_q2[tid], (double)q);
}

__global__ void k_fold2(const float* __restrict__ W3, const float* __restrict__ b3,
                        const float* __restrict__ g2, const float* __restrict__ be2){
  __shared__ float al[HH], bt[HH];
  int tid = threadIdx.x;
  double m = g_s2[tid]/(double)NN;
  double v = g_q2[tid]/(double)NN - m*m;
  float a = rsqrtf((float)v + 1e-5f) * g2[tid];
  al[tid] = a; bt[tid] = be2[tid] - (float)m*a;
  __syncthreads();
  if (tid < FF){
    float bb = b3[tid];
    for (int k = 0; k < HH; k++){
      float w = W3[k*FF + tid];
      g_W3f[k*FF + tid] = al[k]*w;
      bb += bt[k]*w;
    }
    g_b3f[tid] = bb;
  }
}

// ---------------- node layer 3: 8 row-accumulators ----------------
__global__ void k_node3(const float* __restrict__ nf){
  __shared__ float a2s[16*HH];    // 8KB
  __shared__ float w3s[HH*FF];    // 32KB
  int tid = threadIdx.x;
  int r0  = blockIdx.x*16;
  for (int i = tid; i < 16*HH; i += 128) a2s[i] = g_A2[r0*HH + i];
  for (int i = tid; i < HH*FF; i += 128) w3s[i] = g_W3f[i];
  __syncthreads();
  int c = tid & 63, rh = tid >> 6;
  float acc[8];
  #pragma unroll
  for (int r = 0; r < 8; r++) acc[r] = 0.f;
  for (int kb = 0; kb < HH; kb += 8){
    float w0 = w3s[(kb+0)*FF+c], w1 = w3s[(kb+1)*FF+c];
    float w2 = w3s[(kb+2)*FF+c], w3 = w3s[(kb+3)*FF+c];
    float w4 = w3s[(kb+4)*FF+c], w5 = w3s[(kb+5)*FF+c];
    float w6 = w3s[(kb+6)*FF+c], w7 = w3s[(kb+7)*FF+c];
    #pragma unroll
    for (int r = 0; r < 8; r++){
      const float* ar = a2s + (rh*8+r)*HH + kb;
      float p0 = ar[0]*w0 + ar[1]*w1;
      float p1 = ar[2]*w2 + ar[3]*w3;
      float p2 = ar[4]*w4 + ar[5]*w5;
      float p3 = ar[6]*w6 + ar[7]*w7;
      acc[r] += (p0+p1) + (p2+p3);
    }
  }
  #pragma unroll
  for (int r = 0; r < 8; r++){
    int rr = rh*8 + r;
    g_H3[(r0+rr)*FF + c] = acc[r] + g_b3f[c] + nf[(r0+rr)*FF + c];
  }
}

// ---------------- fold BN5 into W6 ----------------
__global__ void k_fold5(const float* __restrict__ W6, const float* __restrict__ b6,
                        const float* __restrict__ g5, const float* __restrict__ be5){
  __shared__ float bt[HH];
  int tid = threadIdx.x;
  double m = g_s5[tid]/EDGEF;
  double v = g_q5[tid]/EDGEF - m*m;
  float a = rsqrtf((float)v + 1e-5f) * g5[tid];
  bt[tid] = be5[tid] - (float)m*a;
  g_W6f[tid*2]     = a*W6[tid*2];
  g_W6f[tid*2 + 1] = a*W6[tid*2 + 1];
  __syncthreads();
  if (tid < 2){
    float bb = b6[tid];
    for (int k = 0; k < HH; k++) bb += bt[k]*W6[k*2 + tid];
    g_b6f[tid] = bb;
  }
}

// ---------------- edge pass 1: fp16 mma.sync m16n8k16 + stats + fp16 t store ----------------
// SMEM floats: W5f 5120 | Hi 32*72=2304 | Hj 2304 | b5s 128 | red 256 | st 8320
#define H_STR   72
#define OFF_W5F 0
#define OFF_HI  5120
#define OFF_HJ  (OFF_HI+2304)
#define OFF_B5  (OFF_HJ+2304)
#define OFF_RED (OFF_B5+128)
#define OFF_ST  (OFF_RED+256)
#define EDGE1_SMEM ((OFF_ST + 8320)*4)   // 73728 bytes

__global__ void __launch_bounds__(256)
k_edgeG(const float* __restrict__ W5, const float* __restrict__ b5){
  extern __shared__ float sm[];
  u32*   w5f = (u32*)(sm + OFF_W5F);      // fragment-order B, lane stride 20 u32
  float* Hi  = sm + OFF_HI;
  float* Hj  = sm + OFF_HJ;
  float* b5s = sm + OFF_B5;
  float* red = sm + OFF_RED;
  u32*   st  = (u32*)(sm + OFF_ST);

  int tid = threadIdx.x;
  int lane = tid & 31, wid = tid >> 5;
  int mg = wid & 3, ng = wid >> 2;
  int qid = lane >> 2, qlane = lane & 3;

  int p = blockIdx.x, bi = 0, rem = p;
  while (rem >= NB - bi){ rem -= NB - bi; bi++; }
  int bj = bi + rem;

  // stage B fragments: for (ng,ks,lane): 16 u32 = b[nt*2+w], w∈{0,1}
  // b = half2( W5[k][n], W5[k+1][n] ), k = ks*16 + qlane*2 + w*8, n = ng*64 + nt*8 + qid
  for (int idx = tid; idx < 4096; idx += 256){
    int g  = idx >> 11;
    int ks = (idx >> 9) & 3;
    int ln = (idx >> 4) & 31;
    int f  = idx & 15;
    int qi = ln >> 2, ql = ln & 3;
    int nt = f >> 1, w = f & 1;
    int k = ks*16 + ql*2 + w*8;
    int n = g*64 + nt*8 + qi;
    __half2 hv = __floats2half2_rn(W5[k*HH + n], W5[(k+1)*HH + n]);
    w5f[((g*4 + ks)*32 + ln)*20 + f] = *(u32*)&hv;
  }
  for (int i = tid; i < TI*FF; i += 256){
    int r = i >> 6, k = i & 63;
    Hi[r*H_STR + k] = g_H3[(bi*TI + r)*FF + k];
    Hj[r*H_STR + k] = g_H3[(bj*TI + r)*FF + k];
  }
  if (tid < HH) b5s[tid] = b5[tid];
  red[tid] = 0.f;
  __syncthreads();

  float ss[16], sq[16];
  #pragma unroll
  for (int i = 0; i < 16; i++){ ss[i] = 0.f; sq[i] = 0.f; }

  for (int t = 0; t < 8; t++){
    float acc[2][8][4];
    #pragma unroll
    for (int mt = 0; mt < 2; mt++)
      #pragma unroll
      for (int nt = 0; nt < 8; nt++)
        #pragma unroll
        for (int c = 0; c < 4; c++) acc[mt][nt][c] = 0.f;

    int ii = t*4 + mg;
    const float2* HiR = (const float2*)(Hi + ii*H_STR);

    #pragma unroll
    for (int ks = 0; ks < 4; ks++){
      const uint4* Bp = (const uint4*)(w5f + ((ng*4 + ks)*32 + lane)*20);
      uint4 B0 = Bp[0], B1 = Bp[1], B2 = Bp[2], B3 = Bp[3];
      u32 b[16] = {B0.x,B0.y,B0.z,B0.w, B1.x,B1.y,B1.z,B1.w,
                   B2.x,B2.y,B2.z,B2.w, B3.x,B3.y,B3.z,B3.w};
      int c2 = ks*8 + qlane;
      float2 hiA = HiR[c2], hiB = HiR[c2+4];
      #pragma unroll
      for (int mt = 0; mt < 2; mt++){
        const float2* HjA = (const float2*)(Hj + (mt*16 + qid)*H_STR);
        const float2* HjB = (const float2*)(Hj + (mt*16 + qid + 8)*H_STR);
        float2 jA  = HjA[c2], jB  = HjB[c2];
        float2 jA2 = HjA[c2+4], jB2 = HjB[c2+4];
        __half2 a0h = __floats2half2_rn(hiA.x*jA.x,  hiA.y*jA.y);
        __half2 a1h = __floats2half2_rn(hiA.x*jB.x,  hiA.y*jB.y);
        __half2 a2h = __floats2half2_rn(hiB.x*jA2.x, hiB.y*jA2.y);
        __half2 a3h = __floats2half2_rn(hiB.x*jB2.x, hiB.y*jB2.y);
        u32 a0 = *(u32*)&a0h, a1 = *(u32*)&a1h, a2 = *(u32*)&a2h, a3 = *(u32*)&a3h;
        #pragma unroll
        for (int nt = 0; nt < 8; nt++){
          asm volatile(
            "mma.sync.aligned.m16n8k16.row.col.f32.f16.f16.f32 "
            "{%0,%1,%2,%3},{%4,%5,%6,%7},{%8,%9},{%0,%1,%2,%3};"
            : "+f"(acc[mt][nt][0]), "+f"(acc[mt][nt][1]),
              "+f"(acc[mt][nt][2]), "+f"(acc[mt][nt][3])
            : "r"(a0),"r"(a1),"r"(a2),"r"(a3), "r"(b[2*nt]),"r"(b[2*nt+1]));
        }
      }
    }

    // epilogue: lrelu + bias, stats, pack fp16 into stage
    float b5v[16];
    #pragma unroll
    for (int i = 0; i < 16; i++)
      b5v[i] = b5s[ng*64 + (i>>1)*8 + qlane*2 + (i&1)];

    #pragma unroll
    for (int mt = 0; mt < 2; mt++)
      #pragma unroll
      for (int nt = 0; nt < 8; nt++)
        #pragma unroll
        for (int h = 0; h < 2; h++){
          float tv0 = lrelu(acc[mt][nt][2*h]   + b5v[nt*2]);
          float tv1 = lrelu(acc[mt][nt][2*h+1] + b5v[nt*2+1]);
          int jj = mt*16 + qid + h*8;
          if ((bi < bj) || (jj > ii)){
            ss[nt*2]   += tv0; sq[nt*2]   += tv0*tv0;
            ss[nt*2+1] += tv1; sq[nt*2+1] += tv1*tv1;
          }
          int r  = mg*32 + jj;
          int c2 = ng*32 + nt*4 + qlane;
          __half2 hv = __floats2half2_rn(tv0, tv1);
          st[r*65 + c2] = *(u32*)&hv;
        }
    __syncthreads();

    size_t slotbase = (size_t)p*1024 + (size_t)t*128;
    #pragma unroll 8
    for (int i = tid; i < 8192; i += 256){
      int c2 = i >> 7, r = i & 127;
      g_Tc[(size_t)c2*ES + slotbase + r] = st[r*65 + c2];
    }
    __syncthreads();
  }

  #pragma unroll
  for (int i = 0; i < 16; i++){
    int col = ng*64 + (i>>1)*8 + qlane*2 + (i&1);
    atomicAdd(&red[col], ss[i]);
    atomicAdd(&red[HH + col], sq[i]);
  }
  __syncthreads();
  if (tid < 128){
    atomicAdd(&g_s5[tid], (double)red[tid]);
    atomicAdd(&g_q5[tid], (double)red[HH + tid]);
  }
}

// ---------------- edge pass 2: stream t-cache, projection -> softmax -> scatter ----------------
__global__ void __launch_bounds__(256)
k_edge2h(float* __restrict__ out){
  __shared__ float w0s[HH], w1s[HH];
  __shared__ int sbb[2];
  int tid = threadIdx.x;
  if (tid < HH){ w0s[tid] = g_W6f[tid*2]; w1s[tid] = g_W6f[tid*2 + 1]; }
  int p = blockIdx.x >> 2;
  if (tid == 0){
    int bi = 0, rem = p;
    while (rem >= NB - bi){ rem -= NB - bi; bi++; }
    sbb[0] = bi; sbb[1] = bi + rem;
  }
  __syncthreads();
  int bi = sbb[0], bj = sbb[1];
  int slot = ((blockIdx.x & 3) << 8) | tid;
  int ii = slot >> 5, jj = slot & 31;
  if (bi == bj && jj <= ii) return;

  size_t base = (size_t)p*1024 + slot;
  float l0 = g_b6f[0], l1 = g_b6f[1];
  #pragma unroll 8
  for (int c2 = 0; c2 < 64; c2++){
    u32 v = g_Tc[(size_t)c2*ES + base];
    float2 f = __half22float2(*(__half2*)&v);
    l0 += f.x*w0s[2*c2] + f.y*w0s[2*c2+1];
    l1 += f.x*w1s[2*c2] + f.y*w1s[2*c2+1];
  }
  int gi = bi*TI + ii, gj = bj*TI + jj;
  float q = __expf(l1 - l0);
  float inv = 1.f/(1.f + q);
  float2 pr = make_float2(inv, q*inv);
  float2* o2 = (float2*)out;
  o2[(size_t)gi*NN + gj] = pr;
  o2[(size_t)gj*NN + gi] = pr;
}

// ---------------- launch ----------------
extern "C" void kernel_launch(void* const* d_in, const int* in_sizes, int n_in,
                              void* d_out, int out_size){
  const float* nf  = (const float*)d_in[1];
  const float* W1  = (const float*)d_in[2];
  const float* b1  = (const float*)d_in[3];
  const float* g1  = (const float*)d_in[4];
  const float* be1 = (const float*)d_in[5];
  const float* W2  = (const float*)d_in[6];
  const float* b2  = (const float*)d_in[7];
  const float* g2  = (const float*)d_in[8];
  const float* be2 = (const float*)d_in[9];
  const float* W3  = (const float*)d_in[10];
  const float* b3  = (const float*)d_in[11];
  const float* W5  = (const float*)d_in[12];
  const float* b5  = (const float*)d_in[13];
  const float* g5  = (const float*)d_in[14];
  const float* be5 = (const float*)d_in[15];
  const float* W6  = (const float*)d_in[16];
  const float* b6  = (const float*)d_in[17];
  float* out = (float*)d_out;

  const int N2_SMEM = (HH*HH + 16*HH) * 4;
  cudaFuncSetAttribute(k_node2, cudaFuncAttributeMaxDynamicSharedMemorySize, N2_SMEM);
  cudaFuncSetAttribute(k_edgeG, cudaFuncAttributeMaxDynamicSharedMemorySize, EDGE1_SMEM);

  k_init<<<1, 1024>>>(out);
  k_node1<<<128, 128>>>(nf, W1, b1);
  k_fold1<<<1, 128>>>(W2, b2, g1, be1);
  k_node2<<<128, 128, N2_SMEM>>>();
  k_fold2<<<1, 128>>>(W3, b3, g2, be2);
  k_node3<<<128, 128>>>(nf);
  k_edgeG<<<NPAIR, 256, EDGE1_SMEM>>>(W5, b5);
  k_fold5<<<1, 128>>>(W6, b6, g5, be5);
  k_edge2h<<<NPAIR*4, 256>>>(out);
}

// round 7
// speedup vs baseline: 3.7521x; 1.1775x over previous
#include <cuda_runtime.h>
#include <cuda_fp16.h>
#include <cstdint>

#define NN 2048
#define FF 64
#define HH 128
#define TI 32
#define NB (NN/TI)            // 64
#define NPAIR (NB*(NB+1)/2)   // 2080
#define EDGEF 2096128.0       // NN*(NN-1)/2
#define ES ((size_t)NPAIR*1024)   // 2,129,920 edge slots

typedef unsigned int u32;

// ---------------- scratch ----------------
__device__ float g_A1[NN*HH];
__device__ float g_A2[NN*HH];
__device__ float g_H3[NN*FF];
__device__ float g_W2f[HH*HH];
__device__ float g_b2f[HH];
__device__ float g_W3f[HH*FF];
__device__ float g_b3f[FF];
__device__ float g_W6f[HH*2];
__device__ float g_b6f[2];
__device__ double g_s1[HH], g_q1[HH], g_s2[HH], g_q2[HH], g_s5[HH], g_q5[HH];
// t-cache, column-planar: g_Tc[c2*ES + edge_slot], half2 per u32. 545 MB.
__device__ u32 g_Tc[64*ES];

__device__ __forceinline__ float lrelu(float x){ return x >= 0.f ? x : 0.01f*x; }

// ---------------- init ----------------
__global__ void k_init(float* __restrict__ out){
  int tid = threadIdx.x;
  if (tid < HH){
    g_s1[tid]=0.0; g_q1[tid]=0.0;
    g_s2[tid]=0.0; g_q2[tid]=0.0;
    g_s5[tid]=0.0; g_q5[tid]=0.0;
  }
  for (int i = tid; i < NN; i += blockDim.x){
    size_t d = (size_t)i*(NN+1)*2;
    out[d] = 0.f; out[d+1] = 0.f;
  }
}

// ---------------- node layer 1: 256 blocks x 8 rows ----------------
__global__ void k_node1(const float* __restrict__ nf, const float* __restrict__ W1,
                        const float* __restrict__ b1){
  __shared__ float nfs[8*FF];
  int tid = threadIdx.x;
  int r0  = blockIdx.x*8;
  for (int i = tid; i < 8*FF; i += 128) nfs[i] = nf[r0*FF + i];
  float w[FF];
  #pragma unroll
  for (int k = 0; k < FF; k++) w[k] = W1[k*HH + tid];
  float bc = b1[tid];
  __syncthreads();
  float s = 0.f, q = 0.f;
  #pragma unroll
  for (int r = 0; r < 8; r++){
    float a0=0.f, a1=0.f, a2=0.f, a3=0.f;
    #pragma unroll
    for (int k = 0; k < FF; k += 4){
      a0 += nfs[r*FF+k]*w[k];
      a1 += nfs[r*FF+k+1]*w[k+1];
      a2 += nfs[r*FF+k+2]*w[k+2];
      a3 += nfs[r*FF+k+3]*w[k+3];
    }
    float a = lrelu(bc + (a0+a1) + (a2+a3));
    g_A1[(r0+r)*HH + tid] = a;
    s += a; q += a*a;
  }
  atomicAdd(&g_s1[tid], (double)s);
  atomicAdd(&g_q1[tid], (double)q);
}

__global__ void k_fold1(const float* __restrict__ W2, const float* __restrict__ b2,
                        const float* __restrict__ g1, const float* __restrict__ be1){
  __shared__ float al[HH], bt[HH];
  int tid = threadIdx.x;
  double m = g_s1[tid]/(double)NN;
  double v = g_q1[tid]/(double)NN - m*m;
  float a = rsqrtf((float)v + 1e-5f) * g1[tid];
  al[tid] = a; bt[tid] = be1[tid] - (float)m*a;
  __syncthreads();
  float bb = b2[tid];
  for (int k = 0; k < HH; k++){
    float w = W2[k*HH + tid];
    g_W2f[k*HH + tid] = al[k]*w;
    bb += bt[k]*w;
  }
  g_b2f[tid] = bb;
}

// ---------------- node layer 2: 256 blocks x 8 rows ----------------
__global__ void k_node2(){
  extern __shared__ float sm2[];
  float* w2s = sm2;                 // 16384
  float* a1s = sm2 + HH*HH;         // 1024
  int tid = threadIdx.x;
  int r0  = blockIdx.x*8;
  for (int i = tid; i < HH*HH; i += 128) w2s[i] = g_W2f[i];
  for (int i = tid; i < 8*HH; i += 128) a1s[i] = g_A1[r0*HH + i];
  float bc = g_b2f[tid];
  __syncthreads();
  float acc[8];
  #pragma unroll
  for (int r = 0; r < 8; r++) acc[r] = 0.f;
  for (int kb = 0; kb < HH; kb += 8){
    float w0 = w2s[(kb+0)*HH+tid], w1 = w2s[(kb+1)*HH+tid];
    float w2 = w2s[(kb+2)*HH+tid], w3 = w2s[(kb+3)*HH+tid];
    float w4 = w2s[(kb+4)*HH+tid], w5 = w2s[(kb+5)*HH+tid];
    float w6 = w2s[(kb+6)*HH+tid], w7 = w2s[(kb+7)*HH+tid];
    #pragma unroll
    for (int r = 0; r < 8; r++){
      const float* ar = a1s + r*HH + kb;
      float p0 = ar[0]*w0 + ar[1]*w1;
      float p1 = ar[2]*w2 + ar[3]*w3;
      float p2 = ar[4]*w4 + ar[5]*w5;
      float p3 = ar[6]*w6 + ar[7]*w7;
      acc[r] += (p0+p1) + (p2+p3);
    }
  }
  float s = 0.f, q = 0.f;
  #pragma unroll
  for (int r = 0; r < 8; r++){
    float a = lrelu(acc[r] + bc);
    g_A2[(r0+r)*HH + tid] = a;
    s += a; q += a*a;
  }
  atomicAdd(&g_s2[tid], (double)s);
  atomicAdd(&g_q2[tid], (double)q);
}

__global__ void k_fold2(const float* __restrict__ W3, const float* __restrict__ b3,
                        const float* __restrict__ g2, const float* __restrict__ be2){
  __shared__ float al[HH], bt[HH];
  int tid = threadIdx.x;
  double m = g_s2[tid]/(double)NN;
  double v = g_q2[tid]/(double)NN - m*m;
  float a = rsqrtf((float)v + 1e-5f) * g2[tid];
  al[tid] = a; bt[tid] = be2[tid] - (float)m*a;
  __syncthreads();
  if (tid < FF){
    float bb = b3[tid];
    for (int k = 0; k < HH; k++){
      float w = W3[k*FF + tid];
      g_W3f[k*FF + tid] = al[k]*w;
      bb += bt[k]*w;
    }
    g_b3f[tid] = bb;
  }
}

// ---------------- node layer 3: 256 blocks x 8 rows ----------------
__global__ void k_node3(const float* __restrict__ nf){
  __shared__ float a2s[8*HH];     // 4KB
  __shared__ float w3s[HH*FF];    // 32KB
  int tid = threadIdx.x;
  int r0  = blockIdx.x*8;
  for (int i = tid; i < 8*HH; i += 128) a2s[i] = g_A2[r0*HH + i];
  for (int i = tid; i < HH*FF; i += 128) w3s[i] = g_W3f[i];
  __syncthreads();
  int c = tid & 63, rh = tid >> 6;
  float acc[4];
  #pragma unroll
  for (int r = 0; r < 4; r++) acc[r] = 0.f;
  for (int kb = 0; kb < HH; kb += 8){
    float w0 = w3s[(kb+0)*FF+c], w1 = w3s[(kb+1)*FF+c];
    float w2 = w3s[(kb+2)*FF+c], w3 = w3s[(kb+3)*FF+c];
    float w4 = w3s[(kb+4)*FF+c], w5 = w3s[(kb+5)*FF+c];
    float w6 = w3s[(kb+6)*FF+c], w7 = w3s[(kb+7)*FF+c];
    #pragma unroll
    for (int r = 0; r < 4; r++){
      const float* ar = a2s + (rh*4+r)*HH + kb;
      float p0 = ar[0]*w0 + ar[1]*w1;
      float p1 = ar[2]*w2 + ar[3]*w3;
      float p2 = ar[4]*w4 + ar[5]*w5;
      float p3 = ar[6]*w6 + ar[7]*w7;
      acc[r] += (p0+p1) + (p2+p3);
    }
  }
  #pragma unroll
  for (int r = 0; r < 4; r++){
    int rr = rh*4 + r;
    g_H3[(r0+rr)*FF + c] = acc[r] + g_b3f[c] + nf[(r0+rr)*FF + c];
  }
}

// ---------------- fold BN5 into W6 ----------------
__global__ void k_fold5(const float* __restrict__ W6, const float* __restrict__ b6,
                        const float* __restrict__ g5, const float* __restrict__ be5){
  __shared__ float bt[HH];
  int tid = threadIdx.x;
  double m = g_s5[tid]/EDGEF;
  double v = g_q5[tid]/EDGEF - m*m;
  float a = rsqrtf((float)v + 1e-5f) * g5[tid];
  bt[tid] = be5[tid] - (float)m*a;
  g_W6f[tid*2]     = a*W6[tid*2];
  g_W6f[tid*2 + 1] = a*W6[tid*2 + 1];
  __syncthreads();
  if (tid < 2){
    float bb = b6[tid];
    for (int k = 0; k < HH; k++) bb += bt[k]*W6[k*2 + tid];
    g_b6f[tid] = bb;
  }
}

// ---------------- edge pass 1: fp16 mma m16n8k16, sync-free mainloop, direct STG ----------------
// SMEM floats: W5f 5120 | Hi 32*72=2304 | Hj 2304 | b5s 128 | red 256 = 10112 floats
#define H_STR   72
#define OFF_W5F 0
#define OFF_HI  5120
#define OFF_HJ  (OFF_HI+2304)
#define OFF_B5  (OFF_HJ+2304)
#define OFF_RED (OFF_B5+128)
#define EDGE1_SMEM ((OFF_RED + 256)*4)   // 40448 bytes

__global__ void __launch_bounds__(256)
k_edgeG(const float* __restrict__ W5, const float* __restrict__ b5){
  extern __shared__ float sm[];
  u32*   w5f = (u32*)(sm + OFF_W5F);      // fragment-order B, lane stride 20 u32
  float* Hi  = sm + OFF_HI;
  float* Hj  = sm + OFF_HJ;
  float* b5s = sm + OFF_B5;
  float* red = sm + OFF_RED;

  int tid = threadIdx.x;
  int lane = tid & 31, wid = tid >> 5;
  int mg = wid & 3, ng = wid >> 2;
  int qid = lane >> 2, qlane = lane & 3;

  int p = blockIdx.x, bi = 0, rem = p;
  while (rem >= NB - bi){ rem -= NB - bi; bi++; }
  int bj = bi + rem;

  // stage B fragments: b = half2(W5[k][n], W5[k+1][n]), k = ks*16 + ql*2 + w*8,
  // n = g*64 + nt*8 + qi; layout (g*4+ks, lane)*20 + nt*2+w
  for (int idx = tid; idx < 4096; idx += 256){
    int g  = idx >> 11;
    int ks = (idx >> 9) & 3;
    int ln = (idx >> 4) & 31;
    int f  = idx & 15;
    int qi = ln >> 2, ql = ln & 3;
    int nt = f >> 1, w = f & 1;
    int k = ks*16 + ql*2 + w*8;
    int n = g*64 + nt*8 + qi;
    __half2 hv = __floats2half2_rn(W5[k*HH + n], W5[(k+1)*HH + n]);
    w5f[((g*4 + ks)*32 + ln)*20 + f] = *(u32*)&hv;
  }
  for (int i = tid; i < TI*FF; i += 256){
    int r = i >> 6, k = i & 63;
    Hi[r*H_STR + k] = g_H3[(bi*TI + r)*FF + k];
    Hj[r*H_STR + k] = g_H3[(bj*TI + r)*FF + k];
  }
  if (tid < HH) b5s[tid] = b5[tid];
  red[tid] = 0.f;
  __syncthreads();
  // ---- mainloop: NO barriers below (all smem read-only) ----

  float b5v[16];
  #pragma unroll
  for (int i = 0; i < 16; i++)
    b5v[i] = b5s[ng*64 + (i>>1)*8 + qlane*2 + (i&1)];

  float ss[16], sq[16];
  #pragma unroll
  for (int i = 0; i < 16; i++){ ss[i] = 0.f; sq[i] = 0.f; }

  size_t pbase = (size_t)p*1024;

  for (int t = 0; t < 8; t++){
    float acc[2][8][4];
    #pragma unroll
    for (int mt = 0; mt < 2; mt++)
      #pragma unroll
      for (int nt = 0; nt < 8; nt++)
        #pragma unroll
        for (int c = 0; c < 4; c++) acc[mt][nt][c] = 0.f;

    int ii = t*4 + mg;
    const float2* HiR = (const float2*)(Hi + ii*H_STR);

    #pragma unroll
    for (int ks = 0; ks < 4; ks++){
      const uint4* Bp = (const uint4*)(w5f + ((ng*4 + ks)*32 + lane)*20);
      uint4 B0 = Bp[0], B1 = Bp[1], B2 = Bp[2], B3 = Bp[3];
      u32 b[16] = {B0.x,B0.y,B0.z,B0.w, B1.x,B1.y,B1.z,B1.w,
                   B2.x,B2.y,B2.z,B2.w, B3.x,B3.y,B3.z,B3.w};
      int c2 = ks*8 + qlane;
      float2 hiA = HiR[c2], hiB = HiR[c2+4];
      #pragma unroll
      for (int mt = 0; mt < 2; mt++){
        const float2* HjA = (const float2*)(Hj + (mt*16 + qid)*H_STR);
        const float2* HjB = (const float2*)(Hj + (mt*16 + qid + 8)*H_STR);
        float2 jA  = HjA[c2], jB  = HjB[c2];
        float2 jA2 = HjA[c2+4], jB2 = HjB[c2+4];
        __half2 a0h = __floats2half2_rn(hiA.x*jA.x,  hiA.y*jA.y);
        __half2 a1h = __floats2half2_rn(hiA.x*jB.x,  hiA.y*jB.y);
        __half2 a2h = __floats2half2_rn(hiB.x*jA2.x, hiB.y*jA2.y);
        __half2 a3h = __floats2half2_rn(hiB.x*jB2.x, hiB.y*jB2.y);
        u32 a0 = *(u32*)&a0h, a1 = *(u32*)&a1h, a2 = *(u32*)&a2h, a3 = *(u32*)&a3h;
        #pragma unroll
        for (int nt = 0; nt < 8; nt++){
          asm volatile(
            "mma.sync.aligned.m16n8k16.row.col.f32.f16.f16.f32 "
            "{%0,%1,%2,%3},{%4,%5,%6,%7},{%8,%9},{%0,%1,%2,%3};"
            : "+f"(acc[mt][nt][0]), "+f"(acc[mt][nt][1]),
              "+f"(acc[mt][nt][2]), "+f"(acc[mt][nt][3])
            : "r"(a0),"r"(a1),"r"(a2),"r"(a3), "r"(b[2*nt]),"r"(b[2*nt+1]));
        }
      }
    }

    // epilogue: lrelu + bias, stats, DIRECT fp16 store (32B-sector aligned per quad)
    size_t tbase = pbase + (size_t)t*128 + mg*32;
    if (bi != bj){
      #pragma unroll
      for (int mt = 0; mt < 2; mt++)
        #pragma unroll
        for (int nt = 0; nt < 8; nt++)
          #pragma unroll
          for (int h = 0; h < 2; h++){
            float tv0 = lrelu(acc[mt][nt][2*h]   + b5v[nt*2]);
            float tv1 = lrelu(acc[mt][nt][2*h+1] + b5v[nt*2+1]);
            ss[nt*2]   += tv0; sq[nt*2]   += tv0*tv0;
            ss[nt*2+1] += tv1; sq[nt*2+1] += tv1*tv1;
            int r  = mt*16 + qid + h*8;
            int c2 = ng*32 + nt*4 + qlane;
            __half2 hv = __floats2half2_rn(tv0, tv1);
            g_Tc[(size_t)c2*ES + tbase + r] = *(u32*)&hv;
          }
    } else {
      #pragma unroll
      for (int mt = 0; mt < 2; mt++)
        #pragma unroll
        for (int nt = 0; nt < 8; nt++)
          #pragma unroll
          for (int h = 0; h < 2; h++){
            float tv0 = lrelu(acc[mt][nt][2*h]   + b5v[nt*2]);
            float tv1 = lrelu(acc[mt][nt][2*h+1] + b5v[nt*2+1]);
            int jj = mt*16 + qid + h*8;
            if (jj > ii){
              ss[nt*2]   += tv0; sq[nt*2]   += tv0*tv0;
              ss[nt*2+1] += tv1; sq[nt*2+1] += tv1*tv1;
            }
            int r  = mt*16 + qid + h*8;
            int c2 = ng*32 + nt*4 + qlane;
            __half2 hv = __floats2half2_rn(tv0, tv1);
            g_Tc[(size_t)c2*ES + tbase + r] = *(u32*)&hv;
          }
    }
  }

  #pragma unroll
  for (int i = 0; i < 16; i++){
    int col = ng*64 + (i>>1)*8 + qlane*2 + (i&1);
    atomicAdd(&red[col], ss[i]);
    atomicAdd(&red[HH + col], sq[i]);
  }
  __syncthreads();
  if (tid < 128){
    atomicAdd(&g_s5[tid], (double)red[tid]);
    atomicAdd(&g_q5[tid], (double)red[HH + tid]);
  }
}

// ---------------- edge pass 2: stream t-cache, projection -> softmax -> scatter ----------------
__global__ void __launch_bounds__(256)
k_edge2h(float* __restrict__ out){
  __shared__ float w0s[HH], w1s[HH];
  __shared__ int sbb[2];
  int tid = threadIdx.x;
  if (tid < HH){ w0s[tid] = g_W6f[tid*2]; w1s[tid] = g_W6f[tid*2 + 1]; }
  int p = blockIdx.x >> 2;
  if (tid == 0){
    int bi = 0, rem = p;
    while (rem >= NB - bi){ rem -= NB - bi; bi++; }
    sbb[0] = bi; sbb[1] = bi + rem;
  }
  __syncthreads();
  int bi = sbb[0], bj = sbb[1];
  int slot = ((blockIdx.x & 3) << 8) | tid;
  int ii = slot >> 5, jj = slot & 31;
  if (bi == bj && jj <= ii) return;

  size_t base = (size_t)p*1024 + slot;
  float l0 = g_b6f[0], l1 = g_b6f[1];
  #pragma unroll 8
  for (int c2 = 0; c2 < 64; c2++){
    u32 v = g_Tc[(size_t)c2*ES + base];
    float2 f = __half22float2(*(__half2*)&v);
    l0 += f.x*w0s[2*c2] + f.y*w0s[2*c2+1];
    l1 += f.x*w1s[2*c2] + f.y*w1s[2*c2+1];
  }
  int gi = bi*TI + ii, gj = bj*TI + jj;
  float q = __expf(l1 - l0);
  float inv = 1.f/(1.f + q);
  float2 pr = make_float2(inv, q*inv);
  float2* o2 = (float2*)out;
  o2[(size_t)gi*NN + gj] = pr;
  o2[(size_t)gj*NN + gi] = pr;
}

// ---------------- launch ----------------
extern "C" void kernel_launch(void* const* d_in, const int* in_sizes, int n_in,
                              void* d_out, int out_size){
  const float* nf  = (const float*)d_in[1];
  const float* W1  = (const float*)d_in[2];
  const float* b1  = (const float*)d_in[3];
  const float* g1  = (const float*)d_in[4];
  const float* be1 = (const float*)d_in[5];
  const float* W2  = (const float*)d_in[6];
  const float* b2  = (const float*)d_in[7];
  const float* g2  = (const float*)d_in[8];
  const float* be2 = (const float*)d_in[9];
  const float* W3  = (const float*)d_in[10];
  const float* b3  = (const float*)d_in[11];
  const float* W5  = (const float*)d_in[12];
  const float* b5  = (const float*)d_in[13];
  const float* g5  = (const float*)d_in[14];
  const float* be5 = (const float*)d_in[15];
  const float* W6  = (const float*)d_in[16];
  const float* b6  = (const float*)d_in[17];
  float* out = (float*)d_out;

  const int N2_SMEM = (HH*HH + 8*HH) * 4;
  cudaFuncSetAttribute(k_node2, cudaFuncAttributeMaxDynamicSharedMemorySize, N2_SMEM);
  cudaFuncSetAttribute(k_edgeG, cudaFuncAttributeMaxDynamicSharedMemorySize, EDGE1_SMEM);

  k_init<<<1, 1024>>>(out);
  k_node1<<<256, 128>>>(nf, W1, b1);
  k_fold1<<<1, 128>>>(W2, b2, g1, be1);
  k_node2<<<256, 128, N2_SMEM>>>();
  k_fold2<<<1, 128>>>(W3, b3, g2, be2);
  k_node3<<<256, 128>>>(nf);
  k_edgeG<<<NPAIR, 256, EDGE1_SMEM>>>(W5, b5);
  k_fold5<<<1, 128>>>(W6, b6, g5, be5);
  k_edge2h<<<NPAIR*4, 256>>>(out);
}

// round 8
// speedup vs baseline: 5.2719x; 1.4051x over previous
#include <cuda_runtime.h>
#include <cuda_fp16.h>
#include <cstdint>

#define NN 2048
#define FF 64
#define HH 128
#define TI 32
#define NB (NN/TI)            // 64
#define NPAIR (NB*(NB+1)/2)   // 2080
#define EDGEF 2096128.0       // NN*(NN-1)/2
#define ES ((size_t)NPAIR*1024)   // 2,129,920 edge slots

typedef unsigned int u32;

// ---------------- scratch ----------------
__device__ float g_A1[NN*HH];
__device__ float g_A2[NN*HH];
__device__ float g_H3[NN*FF];
__device__ float g_W2f[HH*HH];
__device__ float g_b2f[HH];
__device__ float g_W3f[HH*FF];
__device__ float g_b3f[FF];
__device__ float g_W6f[HH*2];
__device__ float g_b6f[2];
__device__ double g_s1[HH], g_q1[HH], g_s2[HH], g_q2[HH], g_s5[HH], g_q5[HH];
// t-cache, column-planar: g_Tc[c2*ES + edge_slot], half2 per u32. 545 MB.
// invalid (diagonal jj<=ii) slots hold 0 so plain sums give valid-edge stats.
__device__ u32 g_Tc[64*ES];

__device__ __forceinline__ float lrelu(float x){ return fmaxf(x, 0.01f*x); }

// ---------------- init ----------------
__global__ void k_init(float* __restrict__ out){
  int tid = threadIdx.x;
  if (tid < HH){
    g_s1[tid]=0.0; g_q1[tid]=0.0;
    g_s2[tid]=0.0; g_q2[tid]=0.0;
    g_s5[tid]=0.0; g_q5[tid]=0.0;
  }
  for (int i = tid; i < NN; i += blockDim.x){
    size_t d = (size_t)i*(NN+1)*2;
    out[d] = 0.f; out[d+1] = 0.f;
  }
}

// ---------------- node layer 1: 256 blocks x 8 rows ----------------
__global__ void k_node1(const float* __restrict__ nf, const float* __restrict__ W1,
                        const float* __restrict__ b1){
  __shared__ float nfs[8*FF];
  int tid = threadIdx.x;
  int r0  = blockIdx.x*8;
  for (int i = tid; i < 8*FF; i += 128) nfs[i] = nf[r0*FF + i];
  float w[FF];
  #pragma unroll
  for (int k = 0; k < FF; k++) w[k] = W1[k*HH + tid];
  float bc = b1[tid];
  __syncthreads();
  float s = 0.f, q = 0.f;
  #pragma unroll
  for (int r = 0; r < 8; r++){
    float a0=0.f, a1=0.f, a2=0.f, a3=0.f;
    #pragma unroll
    for (int k = 0; k < FF; k += 4){
      a0 += nfs[r*FF+k]*w[k];
      a1 += nfs[r*FF+k+1]*w[k+1];
      a2 += nfs[r*FF+k+2]*w[k+2];
      a3 += nfs[r*FF+k+3]*w[k+3];
    }
    float a = lrelu(bc + (a0+a1) + (a2+a3));
    g_A1[(r0+r)*HH + tid] = a;
    s += a; q += a*a;
  }
  atomicAdd(&g_s1[tid], (double)s);
  atomicAdd(&g_q1[tid], (double)q);
}

__global__ void k_fold1(const float* __restrict__ W2, const float* __restrict__ b2,
                        const float* __restrict__ g1, const float* __restrict__ be1){
  __shared__ float al[HH], bt[HH];
  int tid = threadIdx.x;
  double m = g_s1[tid]/(double)NN;
  double v = g_q1[tid]/(double)NN - m*m;
  float a = rsqrtf((float)v + 1e-5f) * g1[tid];
  al[tid] = a; bt[tid] = be1[tid] - (float)m*a;
  __syncthreads();
  float bb = b2[tid];
  for (int k = 0; k < HH; k++){
    float w = W2[k*HH + tid];
    g_W2f[k*HH + tid] = al[k]*w;
    bb += bt[k]*w;
  }
  g_b2f[tid] = bb;
}

// ---------------- node layer 2: 256 blocks x 8 rows ----------------
__global__ void k_node2(){
  extern __shared__ float sm2[];
  float* w2s = sm2;                 // 16384
  float* a1s = sm2 + HH*HH;         // 1024
  int tid = threadIdx.x;
  int r0  = blockIdx.x*8;
  for (int i = tid; i < HH*HH; i += 128) w2s[i] = g_W2f[i];
  for (int i = tid; i < 8*HH; i += 128) a1s[i] = g_A1[r0*HH + i];
  float bc = g_b2f[tid];
  __syncthreads();
  float acc[8];
  #pragma unroll
  for (int r = 0; r < 8; r++) acc[r] = 0.f;
  for (int kb = 0; kb < HH; kb += 8){
    float w0 = w2s[(kb+0)*HH+tid], w1 = w2s[(kb+1)*HH+tid];
    float w2 = w2s[(kb+2)*HH+tid], w3 = w2s[(kb+3)*HH+tid];
    float w4 = w2s[(kb+4)*HH+tid], w5 = w2s[(kb+5)*HH+tid];
    float w6 = w2s[(kb+6)*HH+tid], w7 = w2s[(kb+7)*HH+tid];
    #pragma unroll
    for (int r = 0; r < 8; r++){
      const float* ar = a1s + r*HH + kb;
      float p0 = ar[0]*w0 + ar[1]*w1;
      float p1 = ar[2]*w2 + ar[3]*w3;
      float p2 = ar[4]*w4 + ar[5]*w5;
      float p3 = ar[6]*w6 + ar[7]*w7;
      acc[r] += (p0+p1) + (p2+p3);
    }
  }
  float s = 0.f, q = 0.f;
  #pragma unroll
  for (int r = 0; r < 8; r++){
    float a = lrelu(acc[r] + bc);
    g_A2[(r0+r)*HH + tid] = a;
    s += a; q += a*a;
  }
  atomicAdd(&g_s2[tid], (double)s);
  atomicAdd(&g_q2[tid], (double)q);
}

__global__ void k_fold2(const float* __restrict__ W3, const float* __restrict__ b3,
                        const float* __restrict__ g2, const float* __restrict__ be2){
  __shared__ float al[HH], bt[HH];
  int tid = threadIdx.x;
  double m = g_s2[tid]/(double)NN;
  double v = g_q2[tid]/(double)NN - m*m;
  float a = rsqrtf((float)v + 1e-5f) * g2[tid];
  al[tid] = a; bt[tid] = be2[tid] - (float)m*a;
  __syncthreads();
  if (tid < FF){
    float bb = b3[tid];
    for (int k = 0; k < HH; k++){
      float w = W3[k*FF + tid];
      g_W3f[k*FF + tid] = al[k]*w;
      bb += bt[k]*w;
    }
    g_b3f[tid] = bb;
  }
}

// ---------------- node layer 3: 256 blocks x 8 rows ----------------
__global__ void k_node3(const float* __restrict__ nf){
  __shared__ float a2s[8*HH];     // 4KB
  __shared__ float w3s[HH*FF];    // 32KB
  int tid = threadIdx.x;
  int r0  = blockIdx.x*8;
  for (int i = tid; i < 8*HH; i += 128) a2s[i] = g_A2[r0*HH + i];
  for (int i = tid; i < HH*FF; i += 128) w3s[i] = g_W3f[i];
  __syncthreads();
  int c = tid & 63, rh = tid >> 6;
  float acc[4];
  #pragma unroll
  for (int r = 0; r < 4; r++) acc[r] = 0.f;
  for (int kb = 0; kb < HH; kb += 8){
    float w0 = w3s[(kb+0)*FF+c], w1 = w3s[(kb+1)*FF+c];
    float w2 = w3s[(kb+2)*FF+c], w3 = w3s[(kb+3)*FF+c];
    float w4 = w3s[(kb+4)*FF+c], w5 = w3s[(kb+5)*FF+c];
    float w6 = w3s[(kb+6)*FF+c], w7 = w3s[(kb+7)*FF+c];
    #pragma unroll
    for (int r = 0; r < 4; r++){
      const float* ar = a2s + (rh*4+r)*HH + kb;
      float p0 = ar[0]*w0 + ar[1]*w1;
      float p1 = ar[2]*w2 + ar[3]*w3;
      float p2 = ar[4]*w4 + ar[5]*w5;
      float p3 = ar[6]*w6 + ar[7]*w7;
      acc[r] += (p0+p1) + (p2+p3);
    }
  }
  #pragma unroll
  for (int r = 0; r < 4; r++){
    int rr = rh*4 + r;
    g_H3[(r0+rr)*FF + c] = acc[r] + g_b3f[c] + nf[(r0+rr)*FF + c];
  }
}

// ---------------- fold BN5 into W6 ----------------
__global__ void k_fold5(const float* __restrict__ W6, const float* __restrict__ b6,
                        const float* __restrict__ g5, const float* __restrict__ be5){
  __shared__ float bt[HH];
  int tid = threadIdx.x;
  double m = g_s5[tid]/EDGEF;
  double v = g_q5[tid]/EDGEF - m*m;
  float a = rsqrtf((float)v + 1e-5f) * g5[tid];
  bt[tid] = be5[tid] - (float)m*a;
  g_W6f[tid*2]     = a*W6[tid*2];
  g_W6f[tid*2 + 1] = a*W6[tid*2 + 1];
  __syncthreads();
  if (tid < 2){
    float bb = b6[tid];
    for (int k = 0; k < HH; k++) bb += bt[k]*W6[k*2 + tid];
    g_b6f[tid] = bb;
  }
}

// ---------------- edge pass 1: fp16 mma m16n8k16, no stats, 2 blocks/SM ----------------
// SMEM floats: W5f 5120 | Hi 32*72=2304 | Hj 2304 | b5s 128 = 9856 floats
#define H_STR   72
#define OFF_W5F 0
#define OFF_HI  5120
#define OFF_HJ  (OFF_HI+2304)
#define OFF_B5  (OFF_HJ+2304)
#define EDGE1_SMEM ((OFF_B5 + 128)*4)   // 39424 bytes

__global__ void __launch_bounds__(256, 2)
k_edgeG(const float* __restrict__ W5, const float* __restrict__ b5){
  extern __shared__ float sm[];
  u32*   w5f = (u32*)(sm + OFF_W5F);      // fragment-order B, lane stride 20 u32
  float* Hi  = sm + OFF_HI;
  float* Hj  = sm + OFF_HJ;
  float* b5s = sm + OFF_B5;

  int tid = threadIdx.x;
  int lane = tid & 31, wid = tid >> 5;
  int mg = wid & 3, ng = wid >> 2;
  int qid = lane >> 2, qlane = lane & 3;

  int p = blockIdx.x, bi = 0, rem = p;
  while (rem >= NB - bi){ rem -= NB - bi; bi++; }
  int bj = bi + rem;

  // stage B fragments: b = half2(W5[k][n], W5[k+1][n]), k = ks*16 + ql*2 + w*8,
  // n = g*64 + nt*8 + qi; layout (g*4+ks, lane)*20 + nt*2+w
  for (int idx = tid; idx < 4096; idx += 256){
    int g  = idx >> 11;
    int ks = (idx >> 9) & 3;
    int ln = (idx >> 4) & 31;
    int f  = idx & 15;
    int qi = ln >> 2, ql = ln & 3;
    int nt = f >> 1, w = f & 1;
    int k = ks*16 + ql*2 + w*8;
    int n = g*64 + nt*8 + qi;
    __half2 hv = __floats2half2_rn(W5[k*HH + n], W5[(k+1)*HH + n]);
    w5f[((g*4 + ks)*32 + ln)*20 + f] = *(u32*)&hv;
  }
  for (int i = tid; i < TI*FF; i += 256){
    int r = i >> 6, k = i & 63;
    Hi[r*H_STR + k] = g_H3[(bi*TI + r)*FF + k];
    Hj[r*H_STR + k] = g_H3[(bj*TI + r)*FF + k];
  }
  if (tid < HH) b5s[tid] = b5[tid];
  __syncthreads();
  // ---- mainloop: NO barriers below (all smem read-only) ----

  size_t pbase = (size_t)p*1024;
  bool offdiag = (bi != bj);

  for (int t = 0; t < 8; t++){
    float acc[2][8][4];
    #pragma unroll
    for (int mt = 0; mt < 2; mt++)
      #pragma unroll
      for (int nt = 0; nt < 8; nt++)
        #pragma unroll
        for (int c = 0; c < 4; c++) acc[mt][nt][c] = 0.f;

    int ii = t*4 + mg;
    const float2* HiR = (const float2*)(Hi + ii*H_STR);

    #pragma unroll
    for (int ks = 0; ks < 4; ks++){
      const uint4* Bp = (const uint4*)(w5f + ((ng*4 + ks)*32 + lane)*20);
      uint4 B0 = Bp[0], B1 = Bp[1], B2 = Bp[2], B3 = Bp[3];
      u32 b[16] = {B0.x,B0.y,B0.z,B0.w, B1.x,B1.y,B1.z,B1.w,
                   B2.x,B2.y,B2.z,B2.w, B3.x,B3.y,B3.z,B3.w};
      int c2 = ks*8 + qlane;
      float2 hiA = HiR[c2], hiB = HiR[c2+4];
      #pragma unroll
      for (int mt = 0; mt < 2; mt++){
        const float2* HjA = (const float2*)(Hj + (mt*16 + qid)*H_STR);
        const float2* HjB = (const float2*)(Hj + (mt*16 + qid + 8)*H_STR);
        float2 jA  = HjA[c2], jB  = HjB[c2];
        float2 jA2 = HjA[c2+4], jB2 = HjB[c2+4];
        __half2 a0h = __floats2half2_rn(hiA.x*jA.x,  hiA.y*jA.y);
        __half2 a1h = __floats2half2_rn(hiA.x*jB.x,  hiA.y*jB.y);
        __half2 a2h = __floats2half2_rn(hiB.x*jA2.x, hiB.y*jA2.y);
        __half2 a3h = __floats2half2_rn(hiB.x*jB2.x, hiB.y*jB2.y);
        u32 a0 = *(u32*)&a0h, a1 = *(u32*)&a1h, a2 = *(u32*)&a2h, a3 = *(u32*)&a3h;
        #pragma unroll
        for (int nt = 0; nt < 8; nt++){
          asm volatile(
            "mma.sync.aligned.m16n8k16.row.col.f32.f16.f16.f32 "
            "{%0,%1,%2,%3},{%4,%5,%6,%7},{%8,%9},{%0,%1,%2,%3};"
            : "+f"(acc[mt][nt][0]), "+f"(acc[mt][nt][1]),
              "+f"(acc[mt][nt][2]), "+f"(acc[mt][nt][3])
            : "r"(a0),"r"(a1),"r"(a2),"r"(a3), "r"(b[2*nt]),"r"(b[2*nt+1]));
        }
      }
    }

    // epilogue: lrelu + bias, direct fp16 store; invalid diagonal slots get 0
    size_t tbase = pbase + (size_t)t*128 + mg*32;
    #pragma unroll
    for (int nt = 0; nt < 8; nt++){
      float2 bb = *(const float2*)&b5s[ng*64 + nt*8 + qlane*2];
      int c2 = ng*32 + nt*4 + qlane;
      u32* colp = g_Tc + (size_t)c2*ES + tbase;
      #pragma unroll
      for (int mt = 0; mt < 2; mt++)
        #pragma unroll
        for (int h = 0; h < 2; h++){
          float tv0 = lrelu(acc[mt][nt][2*h]   + bb.x);
          float tv1 = lrelu(acc[mt][nt][2*h+1] + bb.y);
          int jj = mt*16 + qid + h*8;
          __half2 hv = __floats2half2_rn(tv0, tv1);
          u32 word = (offdiag || (jj > ii)) ? *(u32*)&hv : 0u;
          colp[jj] = word;
        }
    }
  }
}

// ---------------- stats over t-cache (invalid slots are 0) ----------------
__global__ void __launch_bounds__(256)
k_stats(){
  __shared__ float rs[4*8];
  int blk = blockIdx.x;                 // 256 blocks
  int c2 = blk >> 2, quad = blk & 3;
  const uint4* ptr = (const uint4*)(g_Tc + (size_t)c2*ES + (size_t)quad*(ES/4));
  const int n4 = (int)(ES/4/4);         // 133120
  int tid = threadIdx.x;
  float s0=0.f, q0=0.f, s1=0.f, q1=0.f;
  for (int i = tid; i < n4; i += 256){
    uint4 v = ptr[i];
    float2 f0 = __half22float2(*(__half2*)&v.x);
    float2 f1 = __half22float2(*(__half2*)&v.y);
    float2 f2 = __half22float2(*(__half2*)&v.z);
    float2 f3 = __half22float2(*(__half2*)&v.w);
    s0 += (f0.x + f1.x) + (f2.x + f3.x);
    s1 += (f0.y + f1.y) + (f2.y + f3.y);
    q0 += (f0.x*f0.x + f1.x*f1.x) + (f2.x*f2.x + f3.x*f3.x);
    q1 += (f0.y*f0.y + f1.y*f1.y) + (f2.y*f2.y + f3.y*f3.y);
  }
  #pragma unroll
  for (int off = 16; off >= 1; off >>= 1){
    s0 += __shfl_xor_sync(0xffffffffu, s0, off);
    s1 += __shfl_xor_sync(0xffffffffu, s1, off);
    q0 += __shfl_xor_sync(0xffffffffu, q0, off);
    q1 += __shfl_xor_sync(0xffffffffu, q1, off);
  }
  int wid = tid >> 5;
  if ((tid & 31) == 0){
    rs[wid] = s0; rs[8 + wid] = s1; rs[16 + wid] = q0; rs[24 + wid] = q1;
  }
  __syncthreads();
  if (tid == 0){
    float a0=0.f, a1=0.f, b0=0.f, b1=0.f;
    #pragma unroll
    for (int w = 0; w < 8; w++){ a0+=rs[w]; a1+=rs[8+w]; b0+=rs[16+w]; b1+=rs[24+w]; }
    atomicAdd(&g_s5[2*c2],   (double)a0);
    atomicAdd(&g_s5[2*c2+1], (double)a1);
    atomicAdd(&g_q5[2*c2],   (double)b0);
    atomicAdd(&g_q5[2*c2+1], (double)b1);
  }
}

// ---------------- edge pass 2: stream t-cache, projection -> softmax -> scatter ----------------
__global__ void __launch_bounds__(256)
k_edge2h(float* __restrict__ out){
  __shared__ float w0s[HH], w1s[HH];
  __shared__ int sbb[2];
  int tid = threadIdx.x;
  if (tid < HH){ w0s[tid] = g_W6f[tid*2]; w1s[tid] = g_W6f[tid*2 + 1]; }
  int p = blockIdx.x >> 2;
  if (tid == 0){
    int bi = 0, rem = p;
    while (rem >= NB - bi){ rem -= NB - bi; bi++; }
    sbb[0] = bi; sbb[1] = bi + rem;
  }
  __syncthreads();
  int bi = sbb[0], bj = sbb[1];
  int slot = ((blockIdx.x & 3) << 8) | tid;
  int ii = slot >> 5, jj = slot & 31;
  if (bi == bj && jj <= ii) return;

  size_t base = (size_t)p*1024 + slot;
  float l0 = g_b6f[0], l1 = g_b6f[1];
  #pragma unroll 8
  for (int c2 = 0; c2 < 64; c2++){
    u32 v = g_Tc[(size_t)c2*ES + base];
    float2 f = __half22float2(*(__half2*)&v);
    l0 += f.x*w0s[2*c2] + f.y*w0s[2*c2+1];
    l1 += f.x*w1s[2*c2] + f.y*w1s[2*c2+1];
  }
  int gi = bi*TI + ii, gj = bj*TI + jj;
  float q = __expf(l1 - l0);
  float inv = 1.f/(1.f + q);
  float2 pr = make_float2(inv, q*inv);
  float2* o2 = (float2*)out;
  o2[(size_t)gi*NN + gj] = pr;
  o2[(size_t)gj*NN + gi] = pr;
}

// ---------------- launch ----------------
extern "C" void kernel_launch(void* const* d_in, const int* in_sizes, int n_in,
                              void* d_out, int out_size){
  const float* nf  = (const float*)d_in[1];
  const float* W1  = (const float*)d_in[2];
  const float* b1  = (const float*)d_in[3];
  const float* g1  = (const float*)d_in[4];
  const float* be1 = (const float*)d_in[5];
  const float* W2  = (const float*)d_in[6];
  const float* b2  = (const float*)d_in[7];
  const float* g2  = (const float*)d_in[8];
  const float* be2 = (const float*)d_in[9];
  const float* W3  = (const float*)d_in[10];
  const float* b3  = (const float*)d_in[11];
  const float* W5  = (const float*)d_in[12];
  const float* b5  = (const float*)d_in[13];
  const float* g5  = (const float*)d_in[14];
  const float* be5 = (const float*)d_in[15];
  const float* W6  = (const float*)d_in[16];
  const float* b6  = (const float*)d_in[17];
  float* out = (float*)d_out;

  const int N2_SMEM = (HH*HH + 8*HH) * 4;
  cudaFuncSetAttribute(k_node2, cudaFuncAttributeMaxDynamicSharedMemorySize, N2_SMEM);
  cudaFuncSetAttribute(k_edgeG, cudaFuncAttributeMaxDynamicSharedMemorySize, EDGE1_SMEM);

  k_init<<<1, 1024>>>(out);
  k_node1<<<256, 128>>>(nf, W1, b1);
  k_fold1<<<1, 128>>>(W2, b2, g1, be1);
  k_node2<<<256, 128, N2_SMEM>>>();
  k_fold2<<<1, 128>>>(W3, b3, g2, be2);
  k_node3<<<256, 128>>>(nf);
  k_edgeG<<<NPAIR, 256, EDGE1_SMEM>>>(W5, b5);
  k_stats<<<256, 256>>>();
  k_fold5<<<1, 128>>>(W6, b6, g5, be5);
  k_edge2h<<<NPAIR*4, 256>>>(out);
}

// round 9
// speedup vs baseline: 5.3457x; 1.0140x over previous
#include <cuda_runtime.h>
#include <cuda_fp16.h>
#include <cstdint>

#define NN 2048
#define FF 64
#define HH 128
#define TI 32
#define NB (NN/TI)            // 64
#define NPAIR (NB*(NB+1)/2)   // 2080
#define EDGEF 2096128.0       // NN*(NN-1)/2
#define ES ((size_t)NPAIR*1024)   // 2,129,920 edge slots

typedef unsigned int u32;

// ---------------- scratch ----------------
__device__ float g_A1[NN*HH];
__device__ float g_A2[NN*HH];
__device__ float g_H3[NN*FF];
__device__ float g_W2f[HH*HH];
__device__ float g_b2f[HH];
__device__ float g_W3f[HH*FF];
__device__ float g_b3f[FF];
__device__ float g_W6f[HH*2];
__device__ float g_b6f[2];
__device__ double g_s1[HH], g_q1[HH], g_s2[HH], g_q2[HH], g_s5[HH], g_q5[HH];
// t-cache, column-planar: g_Tc[c2*ES + edge_slot], half2 per u32. 545 MB.
__device__ u32 g_Tc[64*ES];

__device__ __forceinline__ float lrelu(float x){ return fmaxf(x, 0.01f*x); }

// ---------------- init ----------------
__global__ void k_init(float* __restrict__ out){
  int tid = threadIdx.x;
  if (tid < HH){
    g_s1[tid]=0.0; g_q1[tid]=0.0;
    g_s2[tid]=0.0; g_q2[tid]=0.0;
    g_s5[tid]=0.0; g_q5[tid]=0.0;
  }
  for (int i = tid; i < NN; i += blockDim.x){
    size_t d = (size_t)i*(NN+1)*2;
    out[d] = 0.f; out[d+1] = 0.f;
  }
}

// ---------------- node layer 1: 256 blocks x 8 rows ----------------
__global__ void k_node1(const float* __restrict__ nf, const float* __restrict__ W1,
                        const float* __restrict__ b1){
  __shared__ float nfs[8*FF];
  int tid = threadIdx.x;
  int r0  = blockIdx.x*8;
  for (int i = tid; i < 8*FF; i += 128) nfs[i] = nf[r0*FF + i];
  float w[FF];
  #pragma unroll
  for (int k = 0; k < FF; k++) w[k] = W1[k*HH + tid];
  float bc = b1[tid];
  __syncthreads();
  float s = 0.f, q = 0.f;
  #pragma unroll
  for (int r = 0; r < 8; r++){
    float a0=0.f, a1=0.f, a2=0.f, a3=0.f;
    #pragma unroll
    for (int k = 0; k < FF; k += 4){
      a0 += nfs[r*FF+k]*w[k];
      a1 += nfs[r*FF+k+1]*w[k+1];
      a2 += nfs[r*FF+k+2]*w[k+2];
      a3 += nfs[r*FF+k+3]*w[k+3];
    }
    float a = lrelu(bc + (a0+a1) + (a2+a3));
    g_A1[(r0+r)*HH + tid] = a;
    s += a; q += a*a;
  }
  atomicAdd(&g_s1[tid], (double)s);
  atomicAdd(&g_q1[tid], (double)q);
}

__global__ void k_fold1(const float* __restrict__ W2, const float* __restrict__ b2,
                        const float* __restrict__ g1, const float* __restrict__ be1){
  __shared__ float al[HH], bt[HH];
  int tid = threadIdx.x;
  double m = g_s1[tid]/(double)NN;
  double v = g_q1[tid]/(double)NN - m*m;
  float a = rsqrtf((float)v + 1e-5f) * g1[tid];
  al[tid] = a; bt[tid] = be1[tid] - (float)m*a;
  __syncthreads();
  float bb = b2[tid];
  for (int k = 0; k < HH; k++){
    float w = W2[k*HH + tid];
    g_W2f[k*HH + tid] = al[k]*w;
    bb += bt[k]*w;
  }
  g_b2f[tid] = bb;
}

// ---------------- node layer 2: 256 blocks x 8 rows ----------------
__global__ void k_node2(){
  extern __shared__ float sm2[];
  float* w2s = sm2;                 // 16384
  float* a1s = sm2 + HH*HH;         // 1024
  int tid = threadIdx.x;
  int r0  = blockIdx.x*8;
  for (int i = tid; i < HH*HH; i += 128) w2s[i] = g_W2f[i];
  for (int i = tid; i < 8*HH; i += 128) a1s[i] = g_A1[r0*HH + i];
  float bc = g_b2f[tid];
  __syncthreads();
  float acc[8];
  #pragma unroll
  for (int r = 0; r < 8; r++) acc[r] = 0.f;
  for (int kb = 0; kb < HH; kb += 8){
    float w0 = w2s[(kb+0)*HH+tid], w1 = w2s[(kb+1)*HH+tid];
    float w2 = w2s[(kb+2)*HH+tid], w3 = w2s[(kb+3)*HH+tid];
    float w4 = w2s[(kb+4)*HH+tid], w5 = w2s[(kb+5)*HH+tid];
    float w6 = w2s[(kb+6)*HH+tid], w7 = w2s[(kb+7)*HH+tid];
    #pragma unroll
    for (int r = 0; r < 8; r++){
      const float* ar = a1s + r*HH + kb;
      float p0 = ar[0]*w0 + ar[1]*w1;
      float p1 = ar[2]*w2 + ar[3]*w3;
      float p2 = ar[4]*w4 + ar[5]*w5;
      float p3 = ar[6]*w6 + ar[7]*w7;
      acc[r] += (p0+p1) + (p2+p3);
    }
  }
  float s = 0.f, q = 0.f;
  #pragma unroll
  for (int r = 0; r < 8; r++){
    float a = lrelu(acc[r] + bc);
    g_A2[(r0+r)*HH + tid] = a;
    s += a; q += a*a;
  }
  atomicAdd(&g_s2[tid], (double)s);
  atomicAdd(&g_q2[tid], (double)q);
}

__global__ void k_fold2(const float* __restrict__ W3, const float* __restrict__ b3,
                        const float* __restrict__ g2, const float* __restrict__ be2){
  __shared__ float al[HH], bt[HH];
  int tid = threadIdx.x;
  double m = g_s2[tid]/(double)NN;
  double v = g_q2[tid]/(double)NN - m*m;
  float a = rsqrtf((float)v + 1e-5f) * g2[tid];
  al[tid] = a; bt[tid] = be2[tid] - (float)m*a;
  __syncthreads();
  if (tid < FF){
    float bb = b3[tid];
    for (int k = 0; k < HH; k++){
      float w = W3[k*FF + tid];
      g_W3f[k*FF + tid] = al[k]*w;
      bb += bt[k]*w;
    }
    g_b3f[tid] = bb;
  }
}

// ---------------- node layer 3: 256 blocks x 8 rows ----------------
__global__ void k_node3(const float* __restrict__ nf){
  __shared__ float a2s[8*HH];     // 4KB
  __shared__ float w3s[HH*FF];    // 32KB
  int tid = threadIdx.x;
  int r0  = blockIdx.x*8;
  for (int i = tid; i < 8*HH; i += 128) a2s[i] = g_A2[r0*HH + i];
  for (int i = tid; i < HH*FF; i += 128) w3s[i] = g_W3f[i];
  __syncthreads();
  int c = tid & 63, rh = tid >> 6;
  float acc[4];
  #pragma unroll
  for (int r = 0; r < 4; r++) acc[r] = 0.f;
  for (int kb = 0; kb < HH; kb += 8){
    float w0 = w3s[(kb+0)*FF+c], w1 = w3s[(kb+1)*FF+c];
    float w2 = w3s[(kb+2)*FF+c], w3 = w3s[(kb+3)*FF+c];
    float w4 = w3s[(kb+4)*FF+c], w5 = w3s[(kb+5)*FF+c];
    float w6 = w3s[(kb+6)*FF+c], w7 = w3s[(kb+7)*FF+c];
    #pragma unroll
    for (int r = 0; r < 4; r++){
      const float* ar = a2s + (rh*4+r)*HH + kb;
      float p0 = ar[0]*w0 + ar[1]*w1;
      float p1 = ar[2]*w2 + ar[3]*w3;
      float p2 = ar[4]*w4 + ar[5]*w5;
      float p3 = ar[6]*w6 + ar[7]*w7;
      acc[r] += (p0+p1) + (p2+p3);
    }
  }
  #pragma unroll
  for (int r = 0; r < 4; r++){
    int rr = rh*4 + r;
    g_H3[(r0+rr)*FF + c] = acc[r] + g_b3f[c] + nf[(r0+rr)*FF + c];
  }
}

// ---------------- fold BN5 into W6 ----------------
__global__ void k_fold5(const float* __restrict__ W6, const float* __restrict__ b6,
                        const float* __restrict__ g5, const float* __restrict__ be5){
  __shared__ float bt[HH];
  int tid = threadIdx.x;
  double m = g_s5[tid]/EDGEF;
  double v = g_q5[tid]/EDGEF - m*m;
  float a = rsqrtf((float)v + 1e-5f) * g5[tid];
  bt[tid] = be5[tid] - (float)m*a;
  g_W6f[tid*2]     = a*W6[tid*2];
  g_W6f[tid*2 + 1] = a*W6[tid*2 + 1];
  __syncthreads();
  if (tid < 2){
    float bb = b6[tid];
    for (int k = 0; k < HH; k++) bb += bt[k]*W6[k*2 + tid];
    g_b6f[tid] = bb;
  }
}

// ---------------- edge pass 1: fp16 mma m16n8k16, SMEM stats, 2 blocks/SM ----------------
// SMEM floats: W5f 5120 | Hi 2304 | Hj 2304 | b5s 128 | sst 4096 | ssq 4096 = 18048
#define H_STR   72
#define OFF_W5F 0
#define OFF_HI  5120
#define OFF_HJ  (OFF_HI+2304)
#define OFF_B5  (OFF_HJ+2304)
#define OFF_SST (OFF_B5+128)
#define OFF_SSQ (OFF_SST+4096)
#define EDGE1_SMEM ((OFF_SSQ + 4096)*4)   // 72192 bytes

__global__ void __launch_bounds__(256, 2)
k_edgeG(const float* __restrict__ W5, const float* __restrict__ b5){
  extern __shared__ float sm[];
  u32*   w5f = (u32*)(sm + OFF_W5F);      // fragment-order B, lane stride 20 u32
  float* Hi  = sm + OFF_HI;
  float* Hj  = sm + OFF_HJ;
  float* b5s = sm + OFF_B5;
  float* sst = sm + OFF_SST;              // [16][256] per-thread stats partial sums
  float* ssq = sm + OFF_SSQ;

  int tid = threadIdx.x;
  int lane = tid & 31, wid = tid >> 5;
  int mg = wid & 3, ng = wid >> 2;
  int qid = lane >> 2, qlane = lane & 3;

  int p = blockIdx.x, bi = 0, rem = p;
  while (rem >= NB - bi){ rem -= NB - bi; bi++; }
  int bj = bi + rem;

  // stage B fragments: b = half2(W5[k][n], W5[k+1][n]), k = ks*16 + ql*2 + w*8,
  // n = g*64 + nt*8 + qi; layout (g*4+ks, lane)*20 + nt*2+w
  for (int idx = tid; idx < 4096; idx += 256){
    int g  = idx >> 11;
    int ks = (idx >> 9) & 3;
    int ln = (idx >> 4) & 31;
    int f  = idx & 15;
    int qi = ln >> 2, ql = ln & 3;
    int nt = f >> 1, w = f & 1;
    int k = ks*16 + ql*2 + w*8;
    int n = g*64 + nt*8 + qi;
    __half2 hv = __floats2half2_rn(W5[k*HH + n], W5[(k+1)*HH + n]);
    w5f[((g*4 + ks)*32 + ln)*20 + f] = *(u32*)&hv;
  }
  for (int i = tid; i < TI*FF; i += 256){
    int r = i >> 6, k = i & 63;
    Hi[r*H_STR + k] = g_H3[(bi*TI + r)*FF + k];
    Hj[r*H_STR + k] = g_H3[(bj*TI + r)*FF + k];
  }
  if (tid < HH) b5s[tid] = b5[tid];
  #pragma unroll
  for (int i = 0; i < 16; i++){ sst[i*256 + tid] = 0.f; ssq[i*256 + tid] = 0.f; }
  __syncthreads();
  // ---- mainloop: NO barriers (all shared writes hit thread-private slots) ----

  size_t pbase = (size_t)p*1024;
  bool offdiag = (bi != bj);

  for (int t = 0; t < 8; t++){
    float acc[2][8][4];
    #pragma unroll
    for (int mt = 0; mt < 2; mt++)
      #pragma unroll
      for (int nt = 0; nt < 8; nt++)
        #pragma unroll
        for (int c = 0; c < 4; c++) acc[mt][nt][c] = 0.f;

    int ii = t*4 + mg;
    const float2* HiR = (const float2*)(Hi + ii*H_STR);

    #pragma unroll
    for (int ks = 0; ks < 4; ks++){
      const uint4* Bp = (const uint4*)(w5f + ((ng*4 + ks)*32 + lane)*20);
      uint4 B0 = Bp[0], B1 = Bp[1], B2 = Bp[2], B3 = Bp[3];
      u32 b[16] = {B0.x,B0.y,B0.z,B0.w, B1.x,B1.y,B1.z,B1.w,
                   B2.x,B2.y,B2.z,B2.w, B3.x,B3.y,B3.z,B3.w};
      int c2 = ks*8 + qlane;
      float2 hiA = HiR[c2], hiB = HiR[c2+4];
      #pragma unroll
      for (int mt = 0; mt < 2; mt++){
        const float2* HjA = (const float2*)(Hj + (mt*16 + qid)*H_STR);
        const float2* HjB = (const float2*)(Hj + (mt*16 + qid + 8)*H_STR);
        float2 jA  = HjA[c2], jB  = HjB[c2];
        float2 jA2 = HjA[c2+4], jB2 = HjB[c2+4];
        __half2 a0h = __floats2half2_rn(hiA.x*jA.x,  hiA.y*jA.y);
        __half2 a1h = __floats2half2_rn(hiA.x*jB.x,  hiA.y*jB.y);
        __half2 a2h = __floats2half2_rn(hiB.x*jA2.x, hiB.y*jA2.y);
        __half2 a3h = __floats2half2_rn(hiB.x*jB2.x, hiB.y*jB2.y);
        u32 a0 = *(u32*)&a0h, a1 = *(u32*)&a1h, a2 = *(u32*)&a2h, a3 = *(u32*)&a3h;
        #pragma unroll
        for (int nt = 0; nt < 8; nt++){
          asm volatile(
            "mma.sync.aligned.m16n8k16.row.col.f32.f16.f16.f32 "
            "{%0,%1,%2,%3},{%4,%5,%6,%7},{%8,%9},{%0,%1,%2,%3};"
            : "+f"(acc[mt][nt][0]), "+f"(acc[mt][nt][1]),
              "+f"(acc[mt][nt][2]), "+f"(acc[mt][nt][3])
            : "r"(a0),"r"(a1),"r"(a2),"r"(a3), "r"(b[2*nt]),"r"(b[2*nt+1]));
        }
      }
    }

    // epilogue: lrelu + bias, direct fp16 store, masked stats into private SMEM slots
    size_t tbase = pbase + (size_t)t*128 + mg*32;
    #pragma unroll
    for (int nt = 0; nt < 8; nt++){
      float2 bb = *(const float2*)&b5s[ng*64 + nt*8 + qlane*2];
      int c2 = ng*32 + nt*4 + qlane;
      u32* colp = g_Tc + (size_t)c2*ES + tbase;
      float s0 = 0.f, s1 = 0.f, q0 = 0.f, q1 = 0.f;
      #pragma unroll
      for (int mt = 0; mt < 2; mt++)
        #pragma unroll
        for (int h = 0; h < 2; h++){
          float tv0 = lrelu(acc[mt][nt][2*h]   + bb.x);
          float tv1 = lrelu(acc[mt][nt][2*h+1] + bb.y);
          int jj = mt*16 + qid + h*8;
          __half2 hv = __floats2half2_rn(tv0, tv1);
          colp[jj] = *(u32*)&hv;
          if (offdiag || jj > ii){
            s0 += tv0; q0 += tv0*tv0;
            s1 += tv1; q1 += tv1*tv1;
          }
        }
      sst[(nt*2)*256 + tid]   += s0;
      ssq[(nt*2)*256 + tid]   += q0;
      sst[(nt*2+1)*256 + tid] += s1;
      ssq[(nt*2+1)*256 + tid] += q1;
    }
  }

  __syncthreads();
  if (tid < 128){
    int c = tid;
    int cg = c >> 6, nt = (c >> 3) & 7, par = c & 1, ql = (c >> 1) & 3;
    int i = nt*2 + par;
    const float* ps = sst + i*256 + cg*128 + ql;
    const float* pq = ssq + i*256 + cg*128 + ql;
    float s = 0.f, q = 0.f;
    #pragma unroll
    for (int m = 0; m < 32; m++){ s += ps[4*m]; q += pq[4*m]; }
    atomicAdd(&g_s5[c], (double)s);
    atomicAdd(&g_q5[c], (double)q);
  }
}

// ---------------- edge pass 2: one block per pair-tile, coalesced dual-orientation writes ----------------
__global__ void __launch_bounds__(256)
k_edge2h(float* __restrict__ out){
  __shared__ float w0s[HH], w1s[HH];
  __shared__ float2 prs[32*33];
  int tid = threadIdx.x;
  if (tid < HH){ w0s[tid] = g_W6f[tid*2]; w1s[tid] = g_W6f[tid*2 + 1]; }
  int p = blockIdx.x;
  int bi = 0, rem = p;
  while (rem >= NB - bi){ rem -= NB - bi; bi++; }
  int bj = bi + rem;
  float b60 = g_b6f[0], b61 = g_b6f[1];
  __syncthreads();

  #pragma unroll
  for (int s4 = 0; s4 < 4; s4++){
    int slot = s4*256 + tid;
    size_t base = (size_t)p*1024 + slot;
    float l0 = b60, l1 = b61;
    #pragma unroll 8
    for (int c2 = 0; c2 < 64; c2++){
      u32 v = g_Tc[(size_t)c2*ES + base];
      float2 f = __half22float2(*(__half2*)&v);
      l0 += f.x*w0s[2*c2] + f.y*w0s[2*c2+1];
      l1 += f.x*w1s[2*c2] + f.y*w1s[2*c2+1];
    }
    float q = __expf(l1 - l0);
    float inv = 1.f/(1.f + q);
    int ii = slot >> 5, jj = slot & 31;
    prs[ii*33 + jj] = make_float2(inv, q*inv);
  }
  __syncthreads();

  float2* o2 = (float2*)out;
  size_t rowi = (size_t)(bi*TI)*NN + bj*TI;
  size_t rowj = (size_t)(bj*TI)*NN + bi*TI;
  if (bi != bj){
    #pragma unroll
    for (int s4 = 0; s4 < 4; s4++){
      int idx = s4*256 + tid;
      int ii = idx >> 5, jj = idx & 31;
      o2[rowi + (size_t)ii*NN + jj] = prs[ii*33 + jj];
    }
    #pragma unroll
    for (int s4 = 0; s4 < 4; s4++){
      int idx = s4*256 + tid;
      int jj = idx >> 5, ii = idx & 31;
      o2[rowj + (size_t)jj*NN + ii] = prs[ii*33 + jj];
    }
  } else {
    #pragma unroll
    for (int s4 = 0; s4 < 4; s4++){
      int idx = s4*256 + tid;
      int ii = idx >> 5, jj = idx & 31;
      if (jj > ii) o2[rowi + (size_t)ii*NN + jj] = prs[ii*33 + jj];
    }
    #pragma unroll
    for (int s4 = 0; s4 < 4; s4++){
      int idx = s4*256 + tid;
      int jj = idx >> 5, ii = idx & 31;
      if (jj > ii) o2[rowj + (size_t)jj*NN + ii] = prs[ii*33 + jj];
    }
  }
}

// ---------------- launch ----------------
extern "C" void kernel_launch(void* const* d_in, const int* in_sizes, int n_in,
                              void* d_out, int out_size){
  const float* nf  = (const float*)d_in[1];
  const float* W1  = (const float*)d_in[2];
  const float* b1  = (const float*)d_in[3];
  const float* g1  = (const float*)d_in[4];
  const float* be1 = (const float*)d_in[5];
  const float* W2  = (const float*)d_in[6];
  const float* b2  = (const float*)d_in[7];
  const float* g2  = (const float*)d_in[8];
  const float* be2 = (const float*)d_in[9];
  const float* W3  = (const float*)d_in[10];
  const float* b3  = (const float*)d_in[11];
  const float* W5  = (const float*)d_in[12];
  const float* b5  = (const float*)d_in[13];
  const float* g5  = (const float*)d_in[14];
  const float* be5 = (const float*)d_in[15];
  const float* W6  = (const float*)d_in[16];
  const float* b6  = (const float*)d_in[17];
  float* out = (float*)d_out;

  const int N2_SMEM = (HH*HH + 8*HH) * 4;
  cudaFuncSetAttribute(k_node2, cudaFuncAttributeMaxDynamicSharedMemorySize, N2_SMEM);
  cudaFuncSetAttribute(k_edgeG, cudaFuncAttributeMaxDynamicSharedMemorySize, EDGE1_SMEM);

  k_init<<<1, 1024>>>(out);
  k_node1<<<256, 128>>>(nf, W1, b1);
  k_fold1<<<1, 128>>>(W2, b2, g1, be1);
  k_node2<<<256, 128, N2_SMEM>>>();
  k_fold2<<<1, 128>>>(W3, b3, g2, be2);
  k_node3<<<256, 128>>>(nf);
  k_edgeG<<<NPAIR, 256, EDGE1_SMEM>>>(W5, b5);
  k_fold5<<<1, 128>>>(W6, b6, g5, be5);
  k_edge2h<<<NPAIR, 256>>>(out);
}

// round 11
// speedup vs baseline: 5.4746x; 1.0241x over previous
#include <cuda_runtime.h>
#include <cuda_fp16.h>
#include <cstdint>

#define NN 2048
#define FF 64
#define HH 128
#define TI 32
#define NB (NN/TI)            // 64
#define NPAIR (NB*(NB+1)/2)   // 2080
#define EDGEF 2096128.0       // NN*(NN-1)/2
#define ES ((size_t)NPAIR*1024)   // 2,129,920 edge slots

typedef unsigned int u32;

// ---------------- scratch ----------------
__device__ float g_A1[NN*HH];
__device__ float g_A2[NN*HH];
__device__ float g_H3[NN*FF];
__device__ float g_W2f[HH*HH];
__device__ float g_b2f[HH];
__device__ float g_W3f[HH*FF];
__device__ float g_b3f[FF];
__device__ float g_W6f[HH*2];
__device__ float g_b6f[2];
__device__ double g_s1[HH], g_q1[HH], g_s2[HH], g_q2[HH], g_s5[HH], g_q5[HH];
// t-cache, column-planar: g_Tc[c2*ES + edge_slot], half2 per u32. 545 MB.
__device__ u32 g_Tc[64*ES];

__device__ __forceinline__ float lrelu(float x){ return fmaxf(x, 0.01f*x); }

// ---------------- init ----------------
__global__ void k_init(float* __restrict__ out){
  int tid = threadIdx.x;
  if (tid < HH){
    g_s1[tid]=0.0; g_q1[tid]=0.0;
    g_s2[tid]=0.0; g_q2[tid]=0.0;
    g_s5[tid]=0.0; g_q5[tid]=0.0;
  }
  for (int i = tid; i < NN; i += blockDim.x){
    size_t d = (size_t)i*(NN+1)*2;
    out[d] = 0.f; out[d+1] = 0.f;
  }
}

// ---------------- node layer 1: 256 blocks x 8 rows ----------------
__global__ void k_node1(const float* __restrict__ nf, const float* __restrict__ W1,
                        const float* __restrict__ b1){
  __shared__ float nfs[8*FF];
  int tid = threadIdx.x;
  int r0  = blockIdx.x*8;
  for (int i = tid; i < 8*FF; i += 128) nfs[i] = nf[r0*FF + i];
  float w[FF];
  #pragma unroll
  for (int k = 0; k < FF; k++) w[k] = W1[k*HH + tid];
  float bc = b1[tid];
  __syncthreads();
  float s = 0.f, q = 0.f;
  #pragma unroll
  for (int r = 0; r < 8; r++){
    float a0=0.f, a1=0.f, a2=0.f, a3=0.f;
    #pragma unroll
    for (int k = 0; k < FF; k += 4){
      a0 += nfs[r*FF+k]*w[k];
      a1 += nfs[r*FF+k+1]*w[k+1];
      a2 += nfs[r*FF+k+2]*w[k+2];
      a3 += nfs[r*FF+k+3]*w[k+3];
    }
    float a = lrelu(bc + (a0+a1) + (a2+a3));
    g_A1[(r0+r)*HH + tid] = a;
    s += a; q += a*a;
  }
  atomicAdd(&g_s1[tid], (double)s);
  atomicAdd(&g_q1[tid], (double)q);
}

__global__ void k_fold1(const float* __restrict__ W2, const float* __restrict__ b2,
                        const float* __restrict__ g1, const float* __restrict__ be1){
  __shared__ float al[HH], bt[HH];
  int tid = threadIdx.x;
  double m = g_s1[tid]/(double)NN;
  double v = g_q1[tid]/(double)NN - m*m;
  float a = rsqrtf((float)v + 1e-5f) * g1[tid];
  al[tid] = a; bt[tid] = be1[tid] - (float)m*a;
  __syncthreads();
  float bb = b2[tid];
  for (int k = 0; k < HH; k++){
    float w = W2[k*HH + tid];
    g_W2f[k*HH + tid] = al[k]*w;
    bb += bt[k]*w;
  }
  g_b2f[tid] = bb;
}

// ---------------- node layer 2: 256 blocks x 8 rows ----------------
__global__ void k_node2(){
  extern __shared__ float sm2[];
  float* w2s = sm2;                 // 16384
  float* a1s = sm2 + HH*HH;         // 1024
  int tid = threadIdx.x;
  int r0  = blockIdx.x*8;
  for (int i = tid; i < HH*HH; i += 128) w2s[i] = g_W2f[i];
  for (int i = tid; i < 8*HH; i += 128) a1s[i] = g_A1[r0*HH + i];
  float bc = g_b2f[tid];
  __syncthreads();
  float acc[8];
  #pragma unroll
  for (int r = 0; r < 8; r++) acc[r] = 0.f;
  for (int kb = 0; kb < HH; kb += 8){
    float w0 = w2s[(kb+0)*HH+tid], w1 = w2s[(kb+1)*HH+tid];
    float w2 = w2s[(kb+2)*HH+tid], w3 = w2s[(kb+3)*HH+tid];
    float w4 = w2s[(kb+4)*HH+tid], w5 = w2s[(kb+5)*HH+tid];
    float w6 = w2s[(kb+6)*HH+tid], w7 = w2s[(kb+7)*HH+tid];
    #pragma unroll
    for (int r = 0; r < 8; r++){
      const float* ar = a1s + r*HH + kb;
      float p0 = ar[0]*w0 + ar[1]*w1;
      float p1 = ar[2]*w2 + ar[3]*w3;
      float p2 = ar[4]*w4 + ar[5]*w5;
      float p3 = ar[6]*w6 + ar[7]*w7;
      acc[r] += (p0+p1) + (p2+p3);
    }
  }
  float s = 0.f, q = 0.f;
  #pragma unroll
  for (int r = 0; r < 8; r++){
    float a = lrelu(acc[r] + bc);
    g_A2[(r0+r)*HH + tid] = a;
    s += a; q += a*a;
  }
  atomicAdd(&g_s2[tid], (double)s);
  atomicAdd(&g_q2[tid], (double)q);
}

__global__ void k_fold2(const float* __restrict__ W3, const float* __restrict__ b3,
                        const float* __restrict__ g2, const float* __restrict__ be2){
  __shared__ float al[HH], bt[HH];
  int tid = threadIdx.x;
  double m = g_s2[tid]/(double)NN;
  double v = g_q2[tid]/(double)NN - m*m;
  float a = rsqrtf((float)v + 1e-5f) * g2[tid];
  al[tid] = a; bt[tid] = be2[tid] - (float)m*a;
  __syncthreads();
  if (tid < FF){
    float bb = b3[tid];
    for (int k = 0; k < HH; k++){
      float w = W3[k*FF + tid];
      g_W3f[k*FF + tid] = al[k]*w;
      bb += bt[k]*w;
    }
    g_b3f[tid] = bb;
  }
}

// ---------------- node layer 3: 256 blocks x 8 rows ----------------
__global__ void k_node3(const float* __restrict__ nf){
  __shared__ float a2s[8*HH];     // 4KB
  __shared__ float w3s[HH*FF];    // 32KB
  int tid = threadIdx.x;
  int r0  = blockIdx.x*8;
  for (int i = tid; i < 8*HH; i += 128) a2s[i] = g_A2[r0*HH + i];
  for (int i = tid; i < HH*FF; i += 128) w3s[i] = g_W3f[i];
  __syncthreads();
  int c = tid & 63, rh = tid >> 6;
  float acc[4];
  #pragma unroll
  for (int r = 0; r < 4; r++) acc[r] = 0.f;
  for (int kb = 0; kb < HH; kb += 8){
    float w0 = w3s[(kb+0)*FF+c], w1 = w3s[(kb+1)*FF+c];
    float w2 = w3s[(kb+2)*FF+c], w3 = w3s[(kb+3)*FF+c];
    float w4 = w3s[(kb+4)*FF+c], w5 = w3s[(kb+5)*FF+c];
    float w6 = w3s[(kb+6)*FF+c], w7 = w3s[(kb+7)*FF+c];
    #pragma unroll
    for (int r = 0; r < 4; r++){
      const float* ar = a2s + (rh*4+r)*HH + kb;
      float p0 = ar[0]*w0 + ar[1]*w1;
      float p1 = ar[2]*w2 + ar[3]*w3;
      float p2 = ar[4]*w4 + ar[5]*w5;
      float p3 = ar[6]*w6 + ar[7]*w7;
      acc[r] += (p0+p1) + (p2+p3);
    }
  }
  #pragma unroll
  for (int r = 0; r < 4; r++){
    int rr = rh*4 + r;
    g_H3[(r0+rr)*FF + c] = acc[r] + g_b3f[c] + nf[(r0+rr)*FF + c];
  }
}

// ---------------- fold BN5 into W6 ----------------
__global__ void k_fold5(const float* __restrict__ W6, const float* __restrict__ b6,
                        const float* __restrict__ g5, const float* __restrict__ be5){
  __shared__ float bt[HH];
  int tid = threadIdx.x;
  double m = g_s5[tid]/EDGEF;
  double v = g_q5[tid]/EDGEF - m*m;
  float a = rsqrtf((float)v + 1e-5f) * g5[tid];
  bt[tid] = be5[tid] - (float)m*a;
  g_W6f[tid*2]     = a*W6[tid*2];
  g_W6f[tid*2 + 1] = a*W6[tid*2 + 1];
  __syncthreads();
  if (tid < 2){
    float bb = b6[tid];
    for (int k = 0; k < HH; k++) bb += bt[k]*W6[k*2 + tid];
    g_b6f[tid] = bb;
  }
}

// ---------------- edge pass 1: fp16 mma, register stats, halved acc tile, 2 blocks/SM ----------------
// SMEM floats: W5f 5120 | Hi 2304 | Hj 2304 | b5s 128 | sst 4096 | ssq 4096 = 18048
#define H_STR   72
#define OFF_W5F 0
#define OFF_HI  5120
#define OFF_HJ  (OFF_HI+2304)
#define OFF_B5  (OFF_HJ+2304)
#define OFF_SST (OFF_B5+128)
#define OFF_SSQ (OFF_SST+4096)
#define EDGE1_SMEM ((OFF_SSQ + 4096)*4)   // 72192 bytes

__global__ void __launch_bounds__(256, 2)
k_edgeG(const float* __restrict__ W5, const float* __restrict__ b5){
  extern __shared__ float sm[];
  u32*   w5f = (u32*)(sm + OFF_W5F);      // fragment-order B, lane stride 20 u32
  float* Hi  = sm + OFF_HI;
  float* Hj  = sm + OFF_HJ;
  float* b5s = sm + OFF_B5;
  float* sst = sm + OFF_SST;              // [16][256], written once at the end
  float* ssq = sm + OFF_SSQ;

  int tid = threadIdx.x;
  int lane = tid & 31, wid = tid >> 5;
  int mg = wid & 3, ng = wid >> 2;
  int qid = lane >> 2, qlane = lane & 3;

  int p = blockIdx.x, bi = 0, rem = p;
  while (rem >= NB - bi){ rem -= NB - bi; bi++; }
  int bj = bi + rem;

  // stage B fragments: b = half2(W5[k][n], W5[k+1][n]), k = ks*16 + ql*2 + w*8,
  // n = g*64 + nt*8 + qi; layout (g*4+ks, lane)*20 + nt*2+w
  for (int idx = tid; idx < 4096; idx += 256){
    int g  = idx >> 11;
    int ks = (idx >> 9) & 3;
    int ln = (idx >> 4) & 31;
    int f  = idx & 15;
    int qi = ln >> 2, ql = ln & 3;
    int nt = f >> 1, w = f & 1;
    int k = ks*16 + ql*2 + w*8;
    int n = g*64 + nt*8 + qi;
    __half2 hv = __floats2half2_rn(W5[k*HH + n], W5[(k+1)*HH + n]);
    w5f[((g*4 + ks)*32 + ln)*20 + f] = *(u32*)&hv;
  }
  for (int i = tid; i < TI*FF; i += 256){
    int r = i >> 6, k = i & 63;
    Hi[r*H_STR + k] = g_H3[(bi*TI + r)*FF + k];
    Hj[r*H_STR + k] = g_H3[(bj*TI + r)*FF + k];
  }
  if (tid < HH) b5s[tid] = b5[tid];
  __syncthreads();
  // ---- mainloop: NO barriers (smem read-only until final reduction) ----

  size_t pbase = (size_t)p*1024;
  bool offdiag = (bi != bj);

  float ss[16], sq[16];
  #pragma unroll
  for (int i = 0; i < 16; i++){ ss[i] = 0.f; sq[i] = 0.f; }

  for (int t = 0; t < 8; t++){
    int ii = t*4 + mg;
    const float2* HiR = (const float2*)(Hi + ii*H_STR);
    size_t tbase = pbase + (size_t)t*128 + mg*32;

    #pragma unroll
    for (int mh = 0; mh < 2; mh++){
      float acc[8][4];
      #pragma unroll
      for (int nt = 0; nt < 8; nt++)
        #pragma unroll
        for (int c = 0; c < 4; c++) acc[nt][c] = 0.f;

      const float2* HjA = (const float2*)(Hj + (mh*16 + qid)*H_STR);
      const float2* HjB = (const float2*)(Hj + (mh*16 + qid + 8)*H_STR);

      #pragma unroll
      for (int ks = 0; ks < 4; ks++){
        const uint4* Bp = (const uint4*)(w5f + ((ng*4 + ks)*32 + lane)*20);
        uint4 B0 = Bp[0], B1 = Bp[1], B2 = Bp[2], B3 = Bp[3];
        u32 b[16] = {B0.x,B0.y,B0.z,B0.w, B1.x,B1.y,B1.z,B1.w,
                     B2.x,B2.y,B2.z,B2.w, B3.x,B3.y,B3.z,B3.w};
        int c2 = ks*8 + qlane;
        float2 hiA = HiR[c2], hiB = HiR[c2+4];
        float2 jA  = HjA[c2], jB  = HjB[c2];
        float2 jA2 = HjA[c2+4], jB2 = HjB[c2+4];
        __half2 a0h = __floats2half2_rn(hiA.x*jA.x,  hiA.y*jA.y);
        __half2 a1h = __floats2half2_rn(hiA.x*jB.x,  hiA.y*jB.y);
        __half2 a2h = __floats2half2_rn(hiB.x*jA2.x, hiB.y*jA2.y);
        __half2 a3h = __floats2half2_rn(hiB.x*jB2.x, hiB.y*jB2.y);
        u32 a0 = *(u32*)&a0h, a1 = *(u32*)&a1h, a2 = *(u32*)&a2h, a3 = *(u32*)&a3h;
        #pragma unroll
        for (int nt = 0; nt < 8; nt++){
          asm volatile(
            "mma.sync.aligned.m16n8k16.row.col.f32.f16.f16.f32 "
            "{%0,%1,%2,%3},{%4,%5,%6,%7},{%8,%9},{%0,%1,%2,%3};"
            : "+f"(acc[nt][0]), "+f"(acc[nt][1]),
              "+f"(acc[nt][2]), "+f"(acc[nt][3])
            : "r"(a0),"r"(a1),"r"(a2),"r"(a3), "r"(b[2*nt]),"r"(b[2*nt+1]));
        }
      }

      // epilogue mh: lrelu + bias, direct fp16 store, register stats
      #pragma unroll
      for (int nt = 0; nt < 8; nt++){
        float2 bb = *(const float2*)&b5s[ng*64 + nt*8 + qlane*2];
        int c2 = ng*32 + nt*4 + qlane;
        u32* colp = g_Tc + (size_t)c2*ES + tbase;
        #pragma unroll
        for (int h = 0; h < 2; h++){
          float tv0 = lrelu(acc[nt][2*h]   + bb.x);
          float tv1 = lrelu(acc[nt][2*h+1] + bb.y);
          int jj = mh*16 + qid + h*8;
          __half2 hv = __floats2half2_rn(tv0, tv1);
          colp[jj] = *(u32*)&hv;
          if (offdiag || jj > ii){
            ss[nt*2]   += tv0; sq[nt*2]   += tv0*tv0;
            ss[nt*2+1] += tv1; sq[nt*2+1] += tv1*tv1;
          }
        }
      }
    }
  }

  // single SMEM dump + block reduction
  #pragma unroll
  for (int i = 0; i < 16; i++){ sst[i*256 + tid] = ss[i]; ssq[i*256 + tid] = sq[i]; }
  __syncthreads();
  if (tid < 128){
    int c = tid;
    int cg = c >> 6, nt = (c >> 3) & 7, par = c & 1, ql = (c >> 1) & 3;
    int i = nt*2 + par;
    const float* ps = sst + i*256 + cg*128 + ql;
    const float* pq = ssq + i*256 + cg*128 + ql;
    float s = 0.f, q = 0.f;
    #pragma unroll
    for (int m = 0; m < 32; m++){ s += ps[4*m]; q += pq[4*m]; }
    atomicAdd(&g_s5[c], (double)s);
    atomicAdd(&g_q5[c], (double)q);
  }
}

// ---------------- edge pass 2: one block per pair-tile, coalesced dual-orientation writes ----------------
__global__ void __launch_bounds__(256)
k_edge2h(float* __restrict__ out){
  __shared__ float w0s[HH], w1s[HH];
  __shared__ float2 prs[32*33];
  int tid = threadIdx.x;
  if (tid < HH){ w0s[tid] = g_W6f[tid*2]; w1s[tid] = g_W6f[tid*2 + 1]; }
  int p = blockIdx.x;
  int bi = 0, rem = p;
  while (rem >= NB - bi){ rem -= NB - bi; bi++; }
  int bj = bi + rem;
  float b60 = g_b6f[0], b61 = g_b6f[1];
  __syncthreads();

  #pragma unroll
  for (int s4 = 0; s4 < 4; s4++){
    int slot = s4*256 + tid;
    size_t base = (size_t)p*1024 + slot;
    float l0 = b60, l1 = b61;
    #pragma unroll 8
    for (int c2 = 0; c2 < 64; c2++){
      u32 v = g_Tc[(size_t)c2*ES + base];
      float2 f = __half22float2(*(__half2*)&v);
      l0 += f.x*w0s[2*c2] + f.y*w0s[2*c2+1];
      l1 += f.x*w1s[2*c2] + f.y*w1s[2*c2+1];
    }
    float q = __expf(l1 - l0);
    float inv = 1.f/(1.f + q);
    int ii = slot >> 5, jj = slot & 31;
    prs[ii*33 + jj] = make_float2(inv, q*inv);
  }
  __syncthreads();

  float2* o2 = (float2*)out;
  size_t rowi = (size_t)(bi*TI)*NN + bj*TI;
  size_t rowj = (size_t)(bj*TI)*NN + bi*TI;
  if (bi != bj){
    #pragma unroll
    for (int s4 = 0; s4 < 4; s4++){
      int idx = s4*256 + tid;
      int ii = idx >> 5, jj = idx & 31;
      o2[rowi + (size_t)ii*NN + jj] = prs[ii*33 + jj];
    }
    #pragma unroll
    for (int s4 = 0; s4 < 4; s4++){
      int idx = s4*256 + tid;
      int jj = idx >> 5, ii = idx & 31;
      o2[rowj + (size_t)jj*NN + ii] = prs[ii*33 + jj];
    }
  } else {
    #pragma unroll
    for (int s4 = 0; s4 < 4; s4++){
      int idx = s4*256 + tid;
      int ii = idx >> 5, jj = idx & 31;
      if (jj > ii) o2[rowi + (size_t)ii*NN + jj] = prs[ii*33 + jj];
    }
    #pragma unroll
    for (int s4 = 0; s4 < 4; s4++){
      int idx = s4*256 + tid;
      int jj = idx >> 5, ii = idx & 31;
      if (jj > ii) o2[rowj + (size_t)jj*NN + ii] = prs[ii*33 + jj];
    }
  }
}

// ---------------- launch ----------------
extern "C" void kernel_launch(void* const* d_in, const int* in_sizes, int n_in,
                              void* d_out, int out_size){
  const float* nf  = (const float*)d_in[1];
  const float* W1  = (const float*)d_in[2];
  const float* b1  = (const float*)d_in[3];
  const float* g1  = (const float*)d_in[4];
  const float* be1 = (const float*)d_in[5];
  const float* W2  = (const float*)d_in[6];
  const float* b2  = (const float*)d_in[7];
  const float* g2  = (const float*)d_in[8];
  const float* be2 = (const float*)d_in[9];
  const float* W3  = (const float*)d_in[10];
  const float* b3  = (const float*)d_in[11];
  const float* W5  = (const float*)d_in[12];
  const float* b5  = (const float*)d_in[13];
  const float* g5  = (const float*)d_in[14];
  const float* be5 = (const float*)d_in[15];
  const float* W6  = (const float*)d_in[16];
  const float* b6  = (const float*)d_in[17];
  float* out = (float*)d_out;

  const int N2_SMEM = (HH*HH + 8*HH) * 4;
  cudaFuncSetAttribute(k_node2, cudaFuncAttributeMaxDynamicSharedMemorySize, N2_SMEM);
  cudaFuncSetAttribute(k_edgeG, cudaFuncAttributeMaxDynamicSharedMemorySize, EDGE1_SMEM);

  k_init<<<1, 1024>>>(out);
  k_node1<<<256, 128>>>(nf, W1, b1);
  k_fold1<<<1, 128>>>(W2, b2, g1, be1);
  k_node2<<<256, 128, N2_SMEM>>>();
  k_fold2<<<1, 128>>>(W3, b3, g2, be2);
  k_node3<<<256, 128>>>(nf);
  k_edgeG<<<NPAIR, 256, EDGE1_SMEM>>>(W5, b5);
  k_fold5<<<1, 128>>>(W6, b6, g5, be5);
  k_edge2h<<<NPAIR, 256>>>(out);
}